// round 1
// baseline (speedup 1.0000x reference)
#include <cuda_runtime.h>
#include <math.h>
#include <float.h>

// Problem constants
#define TT      2048        // tokens
#define HID     2048        // hidden
#define NHEADS  8
#define HD      256         // head dim
#define QS      2048        // NHEADS*HD
#define KVS     256
#define QKVN    2560        // QS + 2*KVS
#define SCALING 0.0625f     // 256^-0.5

// ---- scratch (static __device__ => no allocations) ----
__device__ float g_qkv[(size_t)TT * QKVN];       // 20 MB
__device__ float g_Q[(size_t)NHEADS * TT * HD];  // 16 MB  [head][t][d]
__device__ float g_K[(size_t)TT * HD];           //  2 MB
__device__ float g_V[(size_t)TT * HD];           //  2 MB
__device__ float g_S[(size_t)NHEADS * TT * TT];  // 128 MB [head][q][k]
__device__ float g_attn[(size_t)TT * QS];        // 16 MB  [t][h*HD+d]

// ============================================================
// Tiled SGEMM, C = alpha * A * B^T   (A[M,K] row-major, B[N,K] row-major)
// BM=BN=64, BK=16, 256 threads, 4x4 micro-tile per thread.
// CAUSAL: skip blocks fully above diagonal; zero masked entries (col>row).
// z-batching via per-z element strides.
// ============================================================
template<bool CAUSAL>
__global__ void gemm_nt(const float* __restrict__ A, const float* __restrict__ B,
                        float* __restrict__ C,
                        int M, int N, int K, int lda, int ldb, int ldc,
                        float alpha, size_t sAz, size_t sBz, size_t sCz)
{
    const int BM = 64, BN = 64, BK = 16;
    A += blockIdx.z * sAz;
    B += blockIdx.z * sBz;
    C += blockIdx.z * sCz;

    const int r0 = blockIdx.y * BM;
    const int c0 = blockIdx.x * BN;
    if (CAUSAL && c0 > r0 + BM - 1) return;   // fully masked: never read downstream

    __shared__ float As[BK][BM + 4];
    __shared__ float Bs[BK][BN + 4];

    const int tid = threadIdx.x;
    const int ty = tid >> 4;          // 0..15
    const int tx = tid & 15;          // 0..15
    const int lr = tid >> 2;          // 0..63 (tile row for loads)
    const int lc = (tid & 3) << 2;    // 0,4,8,12 (k offset for loads)

    float acc[4][4];
    #pragma unroll
    for (int i = 0; i < 4; i++)
        #pragma unroll
        for (int j = 0; j < 4; j++) acc[i][j] = 0.f;

    for (int k0 = 0; k0 < K; k0 += BK) {
        float4 av = *(const float4*)(A + (size_t)(r0 + lr) * lda + k0 + lc);
        float4 bv = *(const float4*)(B + (size_t)(c0 + lr) * ldb + k0 + lc);
        As[lc + 0][lr] = av.x; As[lc + 1][lr] = av.y;
        As[lc + 2][lr] = av.z; As[lc + 3][lr] = av.w;
        Bs[lc + 0][lr] = bv.x; Bs[lc + 1][lr] = bv.y;
        Bs[lc + 2][lr] = bv.z; Bs[lc + 3][lr] = bv.w;
        __syncthreads();

        #pragma unroll
        for (int kk = 0; kk < BK; ++kk) {
            float a[4], b[4];
            #pragma unroll
            for (int i = 0; i < 4; i++) a[i] = As[kk][ty * 4 + i];
            #pragma unroll
            for (int j = 0; j < 4; j++) b[j] = Bs[kk][tx * 4 + j];
            #pragma unroll
            for (int i = 0; i < 4; i++)
                #pragma unroll
                for (int j = 0; j < 4; j++)
                    acc[i][j] += a[i] * b[j];
        }
        __syncthreads();
    }

    #pragma unroll
    for (int i = 0; i < 4; i++) {
        const int r = r0 + ty * 4 + i;
        const int c = c0 + tx * 4;
        float4 v;
        v.x = (CAUSAL && (c + 0) > r) ? 0.f : alpha * acc[i][0];
        v.y = (CAUSAL && (c + 1) > r) ? 0.f : alpha * acc[i][1];
        v.z = (CAUSAL && (c + 2) > r) ? 0.f : alpha * acc[i][2];
        v.w = (CAUSAL && (c + 3) > r) ? 0.f : alpha * acc[i][3];
        *(float4*)(C + (size_t)r * ldc + c) = v;
    }
}

// ============================================================
// Tiled SGEMM, C = A * B   (A[M,K] row-major, B[K,N] row-major)
// CAUSAL_K: limit K loop to r0+BM (probs beyond that are structurally zero).
// ============================================================
template<bool CAUSAL_K>
__global__ void gemm_nn(const float* __restrict__ A, const float* __restrict__ B,
                        float* __restrict__ C,
                        int M, int N, int K, int lda, int ldb, int ldc,
                        size_t sAz, size_t sBz, size_t sCz)
{
    const int BM = 64, BN = 64, BK = 16;
    A += blockIdx.z * sAz;
    B += blockIdx.z * sBz;
    C += blockIdx.z * sCz;

    const int r0 = blockIdx.y * BM;
    const int c0 = blockIdx.x * BN;

    __shared__ float As[BK][BM + 4];
    __shared__ float Bs[BK][BN + 4];

    const int tid = threadIdx.x;
    const int ty = tid >> 4;
    const int tx = tid & 15;
    const int lr = tid >> 2;          // 0..63, A-tile row
    const int lc = (tid & 3) << 2;    // A-tile k offset
    const int bkr = tid >> 4;         // 0..15, B-tile k row
    const int bcc = (tid & 15) << 2;  // 0..60, B-tile col offset

    float acc[4][4];
    #pragma unroll
    for (int i = 0; i < 4; i++)
        #pragma unroll
        for (int j = 0; j < 4; j++) acc[i][j] = 0.f;

    const int kEnd = CAUSAL_K ? min(K, r0 + BM) : K;

    for (int k0 = 0; k0 < kEnd; k0 += BK) {
        float4 av = *(const float4*)(A + (size_t)(r0 + lr) * lda + k0 + lc);
        As[lc + 0][lr] = av.x; As[lc + 1][lr] = av.y;
        As[lc + 2][lr] = av.z; As[lc + 3][lr] = av.w;
        float4 bv = *(const float4*)(B + (size_t)(k0 + bkr) * ldb + c0 + bcc);
        *(float4*)&Bs[bkr][bcc] = bv;
        __syncthreads();

        #pragma unroll
        for (int kk = 0; kk < BK; ++kk) {
            float a[4], b[4];
            #pragma unroll
            for (int i = 0; i < 4; i++) a[i] = As[kk][ty * 4 + i];
            #pragma unroll
            for (int j = 0; j < 4; j++) b[j] = Bs[kk][tx * 4 + j];
            #pragma unroll
            for (int i = 0; i < 4; i++)
                #pragma unroll
                for (int j = 0; j < 4; j++)
                    acc[i][j] += a[i] * b[j];
        }
        __syncthreads();
    }

    #pragma unroll
    for (int i = 0; i < 4; i++) {
        const int r = r0 + ty * 4 + i;
        float4 v = make_float4(acc[i][0], acc[i][1], acc[i][2], acc[i][3]);
        *(float4*)(C + (size_t)r * ldc + c0 + tx * 4) = v;
    }
}

// ============================================================
// RoPE split: qkv[T, 2560] -> g_Q [h][t][d] (roped), g_K (roped), g_V (copy)
// blockIdx.x = t, blockIdx.y = 0..7 (q heads), 8 (k), 9 (v); 128 threads (pairs)
// ============================================================
__global__ void rope_split(const int* __restrict__ positions)
{
    const int t = blockIdx.x;
    const int head = blockIdx.y;
    const int i = threadIdx.x;       // 0..127 (pair index)
    const float* base = g_qkv + (size_t)t * QKVN;

    if (head == 9) {  // V copy
        const float* src = base + QS + KVS;
        g_V[(size_t)t * HD + i] = src[i];
        g_V[(size_t)t * HD + i + 128] = src[i + 128];
        return;
    }

    const float* src = (head < 8) ? (base + head * HD) : (base + QS);
    float* dst = (head < 8) ? (g_Q + ((size_t)head * TT + t) * HD)
                            : (g_K + (size_t)t * HD);

    const float pos = (float)positions[t];
    // inv_freq = 10000^(-2i/256)
    const float inv_freq = expf(-((float)(2 * i) / (float)HD) * logf(10000.0f));
    const float ang = pos * inv_freq;
    const float c = cosf(ang);
    const float s = sinf(ang);
    const float x1 = src[i];
    const float x2 = src[i + 128];
    dst[i]       = x1 * c - x2 * s;
    dst[i + 128] = x2 * c + x1 * s;
}

// ============================================================
// Causal row softmax in place on g_S. grid (T, NHEADS), 256 threads.
// Only touches k in [0, q]; k>q entries were zeroed by the scores epilogue
// (for the diagonal-crossing blocks) or are never read (skipped blocks).
// ============================================================
__global__ void softmax_causal()
{
    const int q = blockIdx.x;
    const int h = blockIdx.y;
    float* row = g_S + ((size_t)h * TT + q) * TT;
    const int n = q + 1;
    const int tid = threadIdx.x;
    __shared__ float red[256];

    float m = -FLT_MAX;
    for (int k = tid; k < n; k += 256) m = fmaxf(m, row[k]);
    red[tid] = m; __syncthreads();
    for (int s = 128; s > 0; s >>= 1) {
        if (tid < s) red[tid] = fmaxf(red[tid], red[tid + s]);
        __syncthreads();
    }
    m = red[0]; __syncthreads();

    float sum = 0.f;
    for (int k = tid; k < n; k += 256) {
        float e = expf(row[k] - m);
        row[k] = e;
        sum += e;
    }
    red[tid] = sum; __syncthreads();
    for (int s = 128; s > 0; s >>= 1) {
        if (tid < s) red[tid] += red[tid + s];
        __syncthreads();
    }
    const float inv = 1.0f / red[0];
    __syncthreads();

    for (int k = tid; k < n; k += 256) row[k] *= inv;
}

// ============================================================
extern "C" void kernel_launch(void* const* d_in, const int* in_sizes, int n_in,
                              void* d_out, int out_size)
{
    const int*   positions = (const int*)d_in[0];
    const float* hidden    = (const float*)d_in[1];
    const float* Wqkv      = (const float*)d_in[2];
    const float* Wo        = (const float*)d_in[3];
    float*       out       = (float*)d_out;

    float *qkv, *Q, *K, *V, *S, *attn;
    cudaGetSymbolAddress((void**)&qkv,  g_qkv);
    cudaGetSymbolAddress((void**)&Q,    g_Q);
    cudaGetSymbolAddress((void**)&K,    g_K);
    cudaGetSymbolAddress((void**)&V,    g_V);
    cudaGetSymbolAddress((void**)&S,    g_S);
    cudaGetSymbolAddress((void**)&attn, g_attn);

    const dim3 blk(256);

    // 1) qkv = hidden @ Wqkv^T   [2048 x 2560]
    gemm_nt<false><<<dim3(QKVN / 64, TT / 64, 1), blk>>>(
        hidden, Wqkv, qkv, TT, QKVN, HID, HID, HID, QKVN, 1.0f, 0, 0, 0);

    // 2) RoPE + split
    rope_split<<<dim3(TT, 10), dim3(128)>>>(positions);

    // 3) scores[h] = scale * Q_h @ K^T  (causal)  [8 x 2048 x 2048]
    gemm_nt<true><<<dim3(TT / 64, TT / 64, NHEADS), blk>>>(
        Q, K, S, TT, TT, HD, HD, HD, TT, SCALING,
        (size_t)TT * HD, 0, (size_t)TT * TT);

    // 4) row softmax (causal)
    softmax_causal<<<dim3(TT, NHEADS), blk>>>();

    // 5) attn[h] = P_h @ V   -> g_attn[t][h*HD + d]
    gemm_nn<true><<<dim3(HD / 64, TT / 64, NHEADS), blk>>>(
        S, V, attn, TT, HD, TT, TT, HD, QS,
        (size_t)TT * TT, 0, (size_t)HD);

    // 6) out = attn @ Wo^T  [2048 x 2048]
    gemm_nt<false><<<dim3(HID / 64, TT / 64, 1), blk>>>(
        attn, Wo, out, TT, HID, QS, QS, QS, HID, 1.0f, 0, 0, 0);
}

// round 3
// speedup vs baseline: 3.2506x; 3.2506x over previous
#include <cuda_runtime.h>
#include <cuda_bf16.h>
#include <math.h>
#include <float.h>
#include <stdint.h>

// ---------------- problem constants ----------------
#define TT      2048
#define HID     2048
#define NHEADS  8
#define HD      256
#define QS      2048
#define KVS     256
#define QKVN    2560
#define SCALING 0.0625f

// ---------------- scratch (static __device__, no allocs) ----------------
__device__ float g_qkv[(size_t)TT * QKVN];
__device__ float g_S[(size_t)NHEADS * TT * TT];

__device__ __nv_bfloat16 g_hid_hi[(size_t)TT * HID],  g_hid_lo[(size_t)TT * HID];
__device__ __nv_bfloat16 g_wqkv_hi[(size_t)QKVN * HID], g_wqkv_lo[(size_t)QKVN * HID];
__device__ __nv_bfloat16 g_wo_hi[(size_t)HID * QS],   g_wo_lo[(size_t)HID * QS];
__device__ __nv_bfloat16 g_Q_hi[(size_t)NHEADS * TT * HD], g_Q_lo[(size_t)NHEADS * TT * HD];
__device__ __nv_bfloat16 g_K_hi[(size_t)TT * HD],     g_K_lo[(size_t)TT * HD];
__device__ __nv_bfloat16 g_Vt_hi[(size_t)HD * TT],    g_Vt_lo[(size_t)HD * TT];
__device__ __nv_bfloat16 g_P_hi[(size_t)NHEADS * TT * TT], g_P_lo[(size_t)NHEADS * TT * TT];
__device__ __nv_bfloat16 g_attn_hi[(size_t)TT * QS],  g_attn_lo[(size_t)TT * QS];

// ---------------- baseline-PTX helpers (sm_80+; NO tcgen05) ----------------
__device__ __forceinline__ uint32_t smem_to_u32(const void* p) {
    uint32_t a;
    asm("{ .reg .u64 t; cvta.to.shared.u64 t, %1; cvt.u32.u64 %0, t; }" : "=r"(a) : "l"(p));
    return a;
}

#define CP_ASYNC16(dst, src) \
    asm volatile("cp.async.cg.shared.global [%0], [%1], 16;" :: "r"(dst), "l"(src) : "memory")
#define CP_COMMIT() asm volatile("cp.async.commit_group;" ::: "memory")
#define CP_WAIT(N)  asm volatile("cp.async.wait_group %0;" :: "n"(N) : "memory")

__device__ __forceinline__ void ldsm_x4(uint32_t& r0, uint32_t& r1, uint32_t& r2, uint32_t& r3,
                                        uint32_t addr) {
    asm volatile("ldmatrix.sync.aligned.m8n8.x4.shared.b16 {%0,%1,%2,%3}, [%4];"
                 : "=r"(r0), "=r"(r1), "=r"(r2), "=r"(r3) : "r"(addr));
}

__device__ __forceinline__ void mma_bf16(float* d, const uint32_t* a, const uint32_t* b) {
    asm volatile("mma.sync.aligned.m16n8k16.row.col.f32.bf16.bf16.f32 "
                 "{%0,%1,%2,%3}, {%4,%5,%6,%7}, {%8,%9}, {%0,%1,%2,%3};"
                 : "+f"(d[0]), "+f"(d[1]), "+f"(d[2]), "+f"(d[3])
                 : "r"(a[0]), "r"(a[1]), "r"(a[2]), "r"(a[3]), "r"(b[0]), "r"(b[1]));
}

// ---------------- smem layout ----------------
// 3 stages; per stage 4 planes (Ahi, Alo, Bhi, Blo); plane = 128 rows x 32 bf16,
// padded row stride 40 bf16 (80B) for conflict-free ldmatrix.
#define ROWP   40
#define PS     (128 * ROWP * 2)      // 10240 B per plane
#define STAGE  (4 * PS)              // 40960 B per stage
#define NSTG   3
#define GEMM_SMEM (NSTG * STAGE)     // 122880 B

// ============================================================
// 3xBF16 warp-MMA GEMM:  C = alpha * A * B^T
// A[M,K] hi/lo planes, B[N,K] hi/lo planes. 128x128 block tile, BK=32.
// 256 threads = 8 warps (4x2); warp tile 32x64.
// CAUSAL:   skip blocks above diagonal, mask epilogue.
// CAUSAL_K: K loop limited to r0+128 (block-causal P*V; P zero-padded).
// EPI: 0 -> fp32 C;  1 -> bf16 hi/lo planes.
// ============================================================
template<bool CAUSAL, bool CAUSAL_K, int EPI>
__global__ void __launch_bounds__(256, 1) gemm_mma3(
    const __nv_bfloat16* __restrict__ Ahi, const __nv_bfloat16* __restrict__ Alo,
    const __nv_bfloat16* __restrict__ Bhi, const __nv_bfloat16* __restrict__ Blo,
    float* __restrict__ C, __nv_bfloat16* __restrict__ Chi, __nv_bfloat16* __restrict__ Clo,
    int K, int lda, int ldb, int ldc, float alpha,
    size_t sAz, size_t sBz, size_t sCz)
{
    const int r0 = blockIdx.y * 128;
    const int c0 = blockIdx.x * 128;
    if (CAUSAL && c0 > r0 + 127) return;

    extern __shared__ char smem[];
    const uint32_t sb = smem_to_u32(smem);

    const int tid  = threadIdx.x;
    const int wid  = tid >> 5;
    const int lane = tid & 31;
    const int wr   = wid >> 1;          // 0..3
    const int wc   = wid & 1;           // 0..1

    const __nv_bfloat16* gp[4];
    gp[0] = Ahi + blockIdx.z * sAz + (size_t)r0 * lda;
    gp[1] = Alo + blockIdx.z * sAz + (size_t)r0 * lda;
    gp[2] = Bhi + blockIdx.z * sBz + (size_t)c0 * ldb;
    gp[3] = Blo + blockIdx.z * sBz + (size_t)c0 * ldb;
    const int ldp[4] = {lda, lda, ldb, ldb};

    const int kEnd = CAUSAL_K ? (r0 + 128) : K;
    const int nc = kEnd >> 5;

    float acc[2][8][4];
    #pragma unroll
    for (int mi = 0; mi < 2; mi++)
        #pragma unroll
        for (int ni = 0; ni < 8; ni++)
            #pragma unroll
            for (int e = 0; e < 4; e++) acc[mi][ni][e] = 0.f;

    // ---- prefetch helper (inlined twice) ----
    auto prefetch = [&](int ci) {
        const int st = ci % NSTG;
        const int k0 = ci << 5;
        #pragma unroll
        for (int p = 0; p < 4; p++) {
            #pragma unroll
            for (int i = 0; i < 2; i++) {
                const int u = tid + i * 256;           // 0..511 uint4 slots
                const int row = u >> 2;
                const int coloff = (u & 3) << 3;       // 0,8,16,24 elems
                const uint32_t daddr = sb + st * STAGE + p * PS + (row * ROWP + coloff) * 2;
                const __nv_bfloat16* src = gp[p] + (size_t)row * ldp[p] + k0 + coloff;
                CP_ASYNC16(daddr, src);
            }
        }
        CP_COMMIT();
    };

    const int npre = (nc < NSTG - 1) ? nc : (NSTG - 1);
    for (int s = 0; s < npre; s++) prefetch(s);

    const int ldj = lane >> 3;   // 0..3 (ldmatrix sub-matrix)
    const int ldr = lane & 7;    // 0..7

    for (int ci = 0; ci < nc; ci++) {
        if (ci + NSTG - 1 < nc) prefetch(ci + NSTG - 1);
        CP_WAIT(NSTG - 2);
        __syncthreads();

        const int st = ci % NSTG;
        const uint32_t Ab = sb + st * STAGE;
        const uint32_t Al = Ab + PS;
        const uint32_t Bb = Ab + 2 * PS;
        const uint32_t Bl = Ab + 3 * PS;

        #pragma unroll
        for (int ks = 0; ks < 2; ks++) {
            uint32_t ah[2][4], al[2][4];
            #pragma unroll
            for (int mi = 0; mi < 2; mi++) {
                const int row = wr * 32 + mi * 16 + (ldj & 1) * 8 + ldr;
                const int col = ks * 16 + (ldj >> 1) * 8;
                const uint32_t off = (row * ROWP + col) * 2;
                ldsm_x4(ah[mi][0], ah[mi][1], ah[mi][2], ah[mi][3], Ab + off);
                ldsm_x4(al[mi][0], al[mi][1], al[mi][2], al[mi][3], Al + off);
            }
            uint32_t bh[8][2], bl[8][2];
            #pragma unroll
            for (int pi = 0; pi < 4; pi++) {
                const int row = wc * 64 + pi * 16 + (ldj >> 1) * 8 + ldr;
                const int col = ks * 16 + (ldj & 1) * 8;
                const uint32_t off = (row * ROWP + col) * 2;
                ldsm_x4(bh[2 * pi][0], bh[2 * pi][1], bh[2 * pi + 1][0], bh[2 * pi + 1][1], Bb + off);
                ldsm_x4(bl[2 * pi][0], bl[2 * pi][1], bl[2 * pi + 1][0], bl[2 * pi + 1][1], Bl + off);
            }
            #pragma unroll
            for (int mi = 0; mi < 2; mi++)
                #pragma unroll
                for (int ni = 0; ni < 8; ni++) {
                    mma_bf16(acc[mi][ni], ah[mi], bh[ni]);   // hi*hi
                    mma_bf16(acc[mi][ni], ah[mi], bl[ni]);   // hi*lo
                    mma_bf16(acc[mi][ni], al[mi], bh[ni]);   // lo*hi
                }
        }
        __syncthreads();
    }

    // ---- epilogue ----
    const int g = lane >> 2;
    const int t = lane & 3;
    #pragma unroll
    for (int mi = 0; mi < 2; mi++) {
        #pragma unroll
        for (int ni = 0; ni < 8; ni++) {
            const int rr = r0 + wr * 32 + mi * 16 + g;
            const int cc = c0 + wc * 64 + ni * 8 + t * 2;
            #pragma unroll
            for (int half = 0; half < 2; half++) {
                const int r = rr + half * 8;
                float v0 = alpha * acc[mi][ni][half * 2 + 0];
                float v1 = alpha * acc[mi][ni][half * 2 + 1];
                if (CAUSAL) {
                    if (cc + 0 > r) v0 = 0.f;
                    if (cc + 1 > r) v1 = 0.f;
                }
                if (EPI == 0) {
                    float2 v; v.x = v0; v.y = v1;
                    *(float2*)(C + blockIdx.z * sCz + (size_t)r * ldc + cc) = v;
                } else {
                    const __nv_bfloat16 h0 = __float2bfloat16(v0);
                    const __nv_bfloat16 h1 = __float2bfloat16(v1);
                    __nv_bfloat162 hv; hv.x = h0; hv.y = h1;
                    __nv_bfloat162 lv;
                    lv.x = __float2bfloat16(v0 - __bfloat162float(h0));
                    lv.y = __float2bfloat16(v1 - __bfloat162float(h1));
                    *(__nv_bfloat162*)(Chi + blockIdx.z * sCz + (size_t)r * ldc + cc) = hv;
                    *(__nv_bfloat162*)(Clo + blockIdx.z * sCz + (size_t)r * ldc + cc) = lv;
                }
            }
        }
    }
}

// ============================================================
// fp32 -> bf16 hi/lo split
// ============================================================
__global__ void conv_planes(const float* __restrict__ src,
                            __nv_bfloat16* __restrict__ hi, __nv_bfloat16* __restrict__ lo, int n)
{
    const int i = blockIdx.x * blockDim.x + threadIdx.x;
    if (i < n) {
        const float x = src[i];
        const __nv_bfloat16 h = __float2bfloat16(x);
        hi[i] = h;
        lo[i] = __float2bfloat16(x - __bfloat162float(h));
    }
}

// ============================================================
// RoPE + split into bf16 hi/lo planes; V transposed.
// ============================================================
__global__ void rope_split_planes(const int* __restrict__ positions)
{
    const int t = blockIdx.x, head = blockIdx.y, i = threadIdx.x;
    const float* base = g_qkv + (size_t)t * QKVN;

    if (head == 9) {
        const float* src = base + QS + KVS;
        #pragma unroll
        for (int hh = 0; hh < 2; hh++) {
            const int d = i + hh * 128;
            const float x = src[d];
            const __nv_bfloat16 h = __float2bfloat16(x);
            g_Vt_hi[(size_t)d * TT + t] = h;
            g_Vt_lo[(size_t)d * TT + t] = __float2bfloat16(x - __bfloat162float(h));
        }
        return;
    }

    const float* src = (head < 8) ? (base + head * HD) : (base + QS);
    const float pos = (float)positions[t];
    const float inv_freq = expf(-((float)(2 * i) / (float)HD) * logf(10000.0f));
    const float ang = pos * inv_freq;
    const float c = cosf(ang), s = sinf(ang);
    const float x1 = src[i], x2 = src[i + 128];
    const float o1 = x1 * c - x2 * s;
    const float o2 = x2 * c + x1 * s;

    __nv_bfloat16 *dh, *dl;
    size_t off;
    if (head < 8) { off = ((size_t)head * TT + t) * HD; dh = g_Q_hi; dl = g_Q_lo; }
    else          { off = (size_t)t * HD;               dh = g_K_hi; dl = g_K_lo; }

    __nv_bfloat16 h1 = __float2bfloat16(o1);
    dh[off + i] = h1;
    dl[off + i] = __float2bfloat16(o1 - __bfloat162float(h1));
    __nv_bfloat16 h2 = __float2bfloat16(o2);
    dh[off + i + 128] = h2;
    dl[off + i + 128] = __float2bfloat16(o2 - __bfloat162float(h2));
}

// ============================================================
// Causal softmax on g_S -> bf16 hi/lo P planes, zero-padded to 128 boundary.
// ============================================================
__global__ void softmax_planes()
{
    const int q = blockIdx.x, h = blockIdx.y, tid = threadIdx.x;
    const float* row = g_S + ((size_t)h * TT + q) * TT;
    const int n = q + 1;
    const int npad = (q & ~127) + 128;
    __shared__ float red[256];

    float m = -FLT_MAX;
    for (int k = tid; k < n; k += 256) m = fmaxf(m, row[k]);
    red[tid] = m; __syncthreads();
    for (int s = 128; s > 0; s >>= 1) {
        if (tid < s) red[tid] = fmaxf(red[tid], red[tid + s]);
        __syncthreads();
    }
    m = red[0]; __syncthreads();

    float e[8];
    float sum = 0.f;
    int cnt = 0;
    for (int k = tid; k < n; k += 256) { const float ev = __expf(row[k] - m); e[cnt++] = ev; sum += ev; }
    red[tid] = sum; __syncthreads();
    for (int s = 128; s > 0; s >>= 1) {
        if (tid < s) red[tid] += red[tid + s];
        __syncthreads();
    }
    const float inv = 1.0f / red[0];

    __nv_bfloat16* ph = g_P_hi + ((size_t)h * TT + q) * TT;
    __nv_bfloat16* pl = g_P_lo + ((size_t)h * TT + q) * TT;
    cnt = 0;
    for (int k = tid; k < npad; k += 256) {
        const float p = (k < n) ? e[cnt++] * inv : 0.f;
        const __nv_bfloat16 hb = __float2bfloat16(p);
        ph[k] = hb;
        pl[k] = __float2bfloat16(p - __bfloat162float(hb));
    }
}

// ============================================================
extern "C" void kernel_launch(void* const* d_in, const int* in_sizes, int n_in,
                              void* d_out, int out_size)
{
    const int*   positions = (const int*)d_in[0];
    const float* hidden    = (const float*)d_in[1];
    const float* Wqkv      = (const float*)d_in[2];
    const float* Wo        = (const float*)d_in[3];
    float*       out       = (float*)d_out;

    float *qkv, *S;
    __nv_bfloat16 *hh, *hl, *wqh, *wql, *woh, *wol, *Qh, *Ql, *Kh, *Kl, *Vth, *Vtl,
                  *Ph, *Pl, *Ath, *Atl;
    cudaGetSymbolAddress((void**)&qkv, g_qkv);
    cudaGetSymbolAddress((void**)&S,   g_S);
    cudaGetSymbolAddress((void**)&hh,  g_hid_hi);  cudaGetSymbolAddress((void**)&hl,  g_hid_lo);
    cudaGetSymbolAddress((void**)&wqh, g_wqkv_hi); cudaGetSymbolAddress((void**)&wql, g_wqkv_lo);
    cudaGetSymbolAddress((void**)&woh, g_wo_hi);   cudaGetSymbolAddress((void**)&wol, g_wo_lo);
    cudaGetSymbolAddress((void**)&Qh,  g_Q_hi);    cudaGetSymbolAddress((void**)&Ql,  g_Q_lo);
    cudaGetSymbolAddress((void**)&Kh,  g_K_hi);    cudaGetSymbolAddress((void**)&Kl,  g_K_lo);
    cudaGetSymbolAddress((void**)&Vth, g_Vt_hi);   cudaGetSymbolAddress((void**)&Vtl, g_Vt_lo);
    cudaGetSymbolAddress((void**)&Ph,  g_P_hi);    cudaGetSymbolAddress((void**)&Pl,  g_P_lo);
    cudaGetSymbolAddress((void**)&Ath, g_attn_hi); cudaGetSymbolAddress((void**)&Atl, g_attn_lo);

    cudaFuncSetAttribute(gemm_mma3<false, false, 0>, cudaFuncAttributeMaxDynamicSharedMemorySize, GEMM_SMEM);
    cudaFuncSetAttribute(gemm_mma3<true,  false, 0>, cudaFuncAttributeMaxDynamicSharedMemorySize, GEMM_SMEM);
    cudaFuncSetAttribute(gemm_mma3<false, true,  1>, cudaFuncAttributeMaxDynamicSharedMemorySize, GEMM_SMEM);

    // 0) fp32 -> bf16 hi/lo planes
    {
        int n1 = TT * HID;   conv_planes<<<(n1 + 255) / 256, 256>>>(hidden, hh, hl, n1);
        int n2 = QKVN * HID; conv_planes<<<(n2 + 255) / 256, 256>>>(Wqkv, wqh, wql, n2);
        int n3 = HID * QS;   conv_planes<<<(n3 + 255) / 256, 256>>>(Wo, woh, wol, n3);
    }

    // 1) qkv = hidden @ Wqkv^T  [2048 x 2560] fp32
    gemm_mma3<false, false, 0><<<dim3(QKVN / 128, TT / 128, 1), 256, GEMM_SMEM>>>(
        hh, hl, wqh, wql, qkv, nullptr, nullptr,
        HID, HID, HID, QKVN, 1.0f, 0, 0, 0);

    // 2) RoPE + split into planes (V transposed)
    rope_split_planes<<<dim3(TT, 10), 128>>>(positions);

    // 3) scores[h] = scale * Q_h @ K^T (causal) -> fp32 g_S
    gemm_mma3<true, false, 0><<<dim3(TT / 128, TT / 128, NHEADS), 256, GEMM_SMEM>>>(
        Qh, Ql, Kh, Kl, S, nullptr, nullptr,
        HD, HD, HD, TT, SCALING, (size_t)TT * HD, 0, (size_t)TT * TT);

    // 4) softmax -> P planes
    softmax_planes<<<dim3(TT, NHEADS), 256>>>();

    // 5) attn[h] = P_h @ Vt^T (block-causal K) -> attn planes [t][h*HD+d]
    gemm_mma3<false, true, 1><<<dim3(HD / 128, TT / 128, NHEADS), 256, GEMM_SMEM>>>(
        Ph, Pl, Vth, Vtl, nullptr, Ath, Atl,
        TT, TT, TT, QS, 1.0f, (size_t)TT * TT, 0, (size_t)HD);

    // 6) out = attn @ Wo^T  [2048 x 2048] fp32
    gemm_mma3<false, false, 0><<<dim3(HID / 128, TT / 128, 1), 256, GEMM_SMEM>>>(
        Ath, Atl, woh, wol, out, nullptr, nullptr,
        QS, QS, QS, HID, 1.0f, 0, 0, 0);
}

// round 4
// speedup vs baseline: 3.6105x; 1.1107x over previous
#include <cuda_runtime.h>
#include <cuda_bf16.h>
#include <math.h>
#include <float.h>
#include <stdint.h>

// ---------------- problem constants ----------------
#define TT      2048
#define HID     2048
#define NHEADS  8
#define HD      256
#define QS      2048
#define KVS     256
#define QKVN    2560
#define SCALING 0.0625f

// ---------------- scratch (static __device__, no allocs) ----------------
__device__ float g_qkv[(size_t)TT * QKVN];
__device__ float g_S[(size_t)NHEADS * TT * TT];

__device__ __nv_bfloat16 g_hid_hi[(size_t)TT * HID],  g_hid_lo[(size_t)TT * HID];
__device__ __nv_bfloat16 g_wqkv_hi[(size_t)QKVN * HID], g_wqkv_lo[(size_t)QKVN * HID];
__device__ __nv_bfloat16 g_wo_hi[(size_t)HID * QS],   g_wo_lo[(size_t)HID * QS];
__device__ __nv_bfloat16 g_Q_hi[(size_t)NHEADS * TT * HD], g_Q_lo[(size_t)NHEADS * TT * HD];
__device__ __nv_bfloat16 g_K_hi[(size_t)TT * HD],     g_K_lo[(size_t)TT * HD];
__device__ __nv_bfloat16 g_Vt_hi[(size_t)HD * TT],    g_Vt_lo[(size_t)HD * TT];
__device__ __nv_bfloat16 g_P_hi[(size_t)NHEADS * TT * TT], g_P_lo[(size_t)NHEADS * TT * TT];
__device__ __nv_bfloat16 g_attn_hi[(size_t)TT * QS],  g_attn_lo[(size_t)TT * QS];

// ---------------- baseline-PTX helpers (sm_80+; NO tcgen05) ----------------
__device__ __forceinline__ uint32_t smem_to_u32(const void* p) {
    uint32_t a;
    asm("{ .reg .u64 t; cvta.to.shared.u64 t, %1; cvt.u32.u64 %0, t; }" : "=r"(a) : "l"(p));
    return a;
}

#define CP_ASYNC16(dst, src) \
    asm volatile("cp.async.cg.shared.global [%0], [%1], 16;" :: "r"(dst), "l"(src) : "memory")
#define CP_COMMIT() asm volatile("cp.async.commit_group;" ::: "memory")
#define CP_WAIT0()  asm volatile("cp.async.wait_group 0;" ::: "memory")

__device__ __forceinline__ void ldsm_x4(uint32_t& r0, uint32_t& r1, uint32_t& r2, uint32_t& r3,
                                        uint32_t addr) {
    asm volatile("ldmatrix.sync.aligned.m8n8.x4.shared.b16 {%0,%1,%2,%3}, [%4];"
                 : "=r"(r0), "=r"(r1), "=r"(r2), "=r"(r3) : "r"(addr));
}

__device__ __forceinline__ void mma_bf16(float* d, const uint32_t* a, const uint32_t* b) {
    asm volatile("mma.sync.aligned.m16n8k16.row.col.f32.bf16.bf16.f32 "
                 "{%0,%1,%2,%3}, {%4,%5,%6,%7}, {%8,%9}, {%0,%1,%2,%3};"
                 : "+f"(d[0]), "+f"(d[1]), "+f"(d[2]), "+f"(d[3])
                 : "r"(a[0]), "r"(a[1]), "r"(a[2]), "r"(a[3]), "r"(b[0]), "r"(b[1]));
}

// ---------------- smem layout ----------------
// 2 stages; per stage 4 planes (Ahi, Alo, Bhi, Blo); plane = 128 rows x 32 bf16,
// padded row stride 40 bf16 (80B) for conflict-free ldmatrix.
#define ROWP   40
#define PS     (128 * ROWP * 2)      // 10240 B per plane
#define STAGE  (4 * PS)              // 40960 B per stage
#define NSTG   2
#define GEMM_SMEM (NSTG * STAGE)     // 81920 B -> 2 CTAs/SM

// ============================================================
// 3xBF16 warp-MMA GEMM:  C = alpha * A * B^T
// A[M,K] hi/lo planes, B[N,K] hi/lo planes. 128x128 block tile, BK=32.
// 256 threads = 8 warps (4x2); warp tile 32x64. 2 CTAs/SM.
// Pipeline order per iter: wait -> sync -> prefetch(next) -> compute  (race-free).
// ============================================================
template<bool CAUSAL, bool CAUSAL_K, int EPI>
__global__ void __launch_bounds__(256, 2) gemm_mma3(
    const __nv_bfloat16* __restrict__ Ahi, const __nv_bfloat16* __restrict__ Alo,
    const __nv_bfloat16* __restrict__ Bhi, const __nv_bfloat16* __restrict__ Blo,
    float* __restrict__ C, __nv_bfloat16* __restrict__ Chi, __nv_bfloat16* __restrict__ Clo,
    int K, int lda, int ldb, int ldc, float alpha,
    size_t sAz, size_t sBz, size_t sCz)
{
    const int r0 = blockIdx.y * 128;
    const int c0 = blockIdx.x * 128;
    if (CAUSAL && c0 > r0 + 127) return;

    extern __shared__ char smem[];
    const uint32_t sb = smem_to_u32(smem);

    const int tid  = threadIdx.x;
    const int wid  = tid >> 5;
    const int lane = tid & 31;
    const int wr   = wid >> 1;          // 0..3
    const int wc   = wid & 1;           // 0..1

    const __nv_bfloat16* gp[4];
    gp[0] = Ahi + blockIdx.z * sAz + (size_t)r0 * lda;
    gp[1] = Alo + blockIdx.z * sAz + (size_t)r0 * lda;
    gp[2] = Bhi + blockIdx.z * sBz + (size_t)c0 * ldb;
    gp[3] = Blo + blockIdx.z * sBz + (size_t)c0 * ldb;
    const int ldp[4] = {lda, lda, ldb, ldb};

    const int kEnd = CAUSAL_K ? (r0 + 128) : K;
    const int nc = kEnd >> 5;

    float acc[2][8][4];
    #pragma unroll
    for (int mi = 0; mi < 2; mi++)
        #pragma unroll
        for (int ni = 0; ni < 8; ni++)
            #pragma unroll
            for (int e = 0; e < 4; e++) acc[mi][ni][e] = 0.f;

    auto prefetch = [&](int ci) {
        const int st = ci & 1;
        const int k0 = ci << 5;
        #pragma unroll
        for (int p = 0; p < 4; p++) {
            #pragma unroll
            for (int i = 0; i < 2; i++) {
                const int u = tid + i * 256;           // 0..511 uint4 slots
                const int row = u >> 2;
                const int coloff = (u & 3) << 3;       // 0,8,16,24 elems
                const uint32_t daddr = sb + st * STAGE + p * PS + (row * ROWP + coloff) * 2;
                const __nv_bfloat16* src = gp[p] + (size_t)row * ldp[p] + k0 + coloff;
                CP_ASYNC16(daddr, src);
            }
        }
        CP_COMMIT();
    };

    if (nc > 0) prefetch(0);

    const int ldj = lane >> 3;   // 0..3
    const int ldr = lane & 7;    // 0..7

    for (int ci = 0; ci < nc; ci++) {
        CP_WAIT0();              // current stage's data landed
        __syncthreads();         // all warps past previous stage's reads + see data
        if (ci + 1 < nc) prefetch(ci + 1);   // overlaps compute below

        const int st = ci & 1;
        const uint32_t Ab = sb + st * STAGE;
        const uint32_t Al = Ab + PS;
        const uint32_t Bb = Ab + 2 * PS;
        const uint32_t Bl = Ab + 3 * PS;

        #pragma unroll
        for (int ks = 0; ks < 2; ks++) {
            uint32_t ah[2][4], al[2][4];
            #pragma unroll
            for (int mi = 0; mi < 2; mi++) {
                const int row = wr * 32 + mi * 16 + (ldj & 1) * 8 + ldr;
                const int col = ks * 16 + (ldj >> 1) * 8;
                const uint32_t off = (row * ROWP + col) * 2;
                ldsm_x4(ah[mi][0], ah[mi][1], ah[mi][2], ah[mi][3], Ab + off);
                ldsm_x4(al[mi][0], al[mi][1], al[mi][2], al[mi][3], Al + off);
            }
            #pragma unroll
            for (int h2 = 0; h2 < 2; h2++) {           // ni halves: 4 ni at a time
                uint32_t bh[4][2], bl[4][2];
                #pragma unroll
                for (int pi = 0; pi < 2; pi++) {
                    const int row = wc * 64 + h2 * 32 + pi * 16 + (ldj >> 1) * 8 + ldr;
                    const int col = ks * 16 + (ldj & 1) * 8;
                    const uint32_t off = (row * ROWP + col) * 2;
                    ldsm_x4(bh[2 * pi][0], bh[2 * pi][1], bh[2 * pi + 1][0], bh[2 * pi + 1][1], Bb + off);
                    ldsm_x4(bl[2 * pi][0], bl[2 * pi][1], bl[2 * pi + 1][0], bl[2 * pi + 1][1], Bl + off);
                }
                // term-outer ordering: 8 independent accumulators between reuses
                #pragma unroll
                for (int mi = 0; mi < 2; mi++)
                    #pragma unroll
                    for (int nl = 0; nl < 4; nl++)
                        mma_bf16(acc[mi][h2 * 4 + nl], ah[mi], bh[nl]);   // hi*hi
                #pragma unroll
                for (int mi = 0; mi < 2; mi++)
                    #pragma unroll
                    for (int nl = 0; nl < 4; nl++)
                        mma_bf16(acc[mi][h2 * 4 + nl], ah[mi], bl[nl]);   // hi*lo
                #pragma unroll
                for (int mi = 0; mi < 2; mi++)
                    #pragma unroll
                    for (int nl = 0; nl < 4; nl++)
                        mma_bf16(acc[mi][h2 * 4 + nl], al[mi], bh[nl]);   // lo*hi
            }
        }
    }

    // ---- epilogue ----
    const int g = lane >> 2;
    const int t = lane & 3;
    #pragma unroll
    for (int mi = 0; mi < 2; mi++) {
        #pragma unroll
        for (int ni = 0; ni < 8; ni++) {
            const int rr = r0 + wr * 32 + mi * 16 + g;
            const int cc = c0 + wc * 64 + ni * 8 + t * 2;
            #pragma unroll
            for (int half = 0; half < 2; half++) {
                const int r = rr + half * 8;
                float v0 = alpha * acc[mi][ni][half * 2 + 0];
                float v1 = alpha * acc[mi][ni][half * 2 + 1];
                if (CAUSAL) {
                    if (cc + 0 > r) v0 = 0.f;
                    if (cc + 1 > r) v1 = 0.f;
                }
                if (EPI == 0) {
                    float2 v; v.x = v0; v.y = v1;
                    *(float2*)(C + blockIdx.z * sCz + (size_t)r * ldc + cc) = v;
                } else {
                    const __nv_bfloat16 h0 = __float2bfloat16(v0);
                    const __nv_bfloat16 h1 = __float2bfloat16(v1);
                    __nv_bfloat162 hv; hv.x = h0; hv.y = h1;
                    __nv_bfloat162 lv;
                    lv.x = __float2bfloat16(v0 - __bfloat162float(h0));
                    lv.y = __float2bfloat16(v1 - __bfloat162float(h1));
                    *(__nv_bfloat162*)(Chi + blockIdx.z * sCz + (size_t)r * ldc + cc) = hv;
                    *(__nv_bfloat162*)(Clo + blockIdx.z * sCz + (size_t)r * ldc + cc) = lv;
                }
            }
        }
    }
}

// ============================================================
__global__ void conv_planes(const float* __restrict__ src,
                            __nv_bfloat16* __restrict__ hi, __nv_bfloat16* __restrict__ lo, int n)
{
    const int i = blockIdx.x * blockDim.x + threadIdx.x;
    if (i < n) {
        const float x = src[i];
        const __nv_bfloat16 h = __float2bfloat16(x);
        hi[i] = h;
        lo[i] = __float2bfloat16(x - __bfloat162float(h));
    }
}

// ============================================================
__global__ void rope_split_planes(const int* __restrict__ positions)
{
    const int t = blockIdx.x, head = blockIdx.y, i = threadIdx.x;
    const float* base = g_qkv + (size_t)t * QKVN;

    if (head == 9) {
        const float* src = base + QS + KVS;
        #pragma unroll
        for (int hh = 0; hh < 2; hh++) {
            const int d = i + hh * 128;
            const float x = src[d];
            const __nv_bfloat16 h = __float2bfloat16(x);
            g_Vt_hi[(size_t)d * TT + t] = h;
            g_Vt_lo[(size_t)d * TT + t] = __float2bfloat16(x - __bfloat162float(h));
        }
        return;
    }

    const float* src = (head < 8) ? (base + head * HD) : (base + QS);
    const float pos = (float)positions[t];
    const float inv_freq = expf(-((float)(2 * i) / (float)HD) * logf(10000.0f));
    const float ang = pos * inv_freq;
    const float c = cosf(ang), s = sinf(ang);
    const float x1 = src[i], x2 = src[i + 128];
    const float o1 = x1 * c - x2 * s;
    const float o2 = x2 * c + x1 * s;

    __nv_bfloat16 *dh, *dl;
    size_t off;
    if (head < 8) { off = ((size_t)head * TT + t) * HD; dh = g_Q_hi; dl = g_Q_lo; }
    else          { off = (size_t)t * HD;               dh = g_K_hi; dl = g_K_lo; }

    __nv_bfloat16 h1 = __float2bfloat16(o1);
    dh[off + i] = h1;
    dl[off + i] = __float2bfloat16(o1 - __bfloat162float(h1));
    __nv_bfloat16 h2 = __float2bfloat16(o2);
    dh[off + i + 128] = h2;
    dl[off + i + 128] = __float2bfloat16(o2 - __bfloat162float(h2));
}

// ============================================================
__global__ void softmax_planes()
{
    const int q = blockIdx.x, h = blockIdx.y, tid = threadIdx.x;
    const float* row = g_S + ((size_t)h * TT + q) * TT;
    const int n = q + 1;
    const int npad = (q & ~127) + 128;
    __shared__ float red[256];

    float m = -FLT_MAX;
    for (int k = tid; k < n; k += 256) m = fmaxf(m, row[k]);
    red[tid] = m; __syncthreads();
    for (int s = 128; s > 0; s >>= 1) {
        if (tid < s) red[tid] = fmaxf(red[tid], red[tid + s]);
        __syncthreads();
    }
    m = red[0]; __syncthreads();

    float e[8];
    float sum = 0.f;
    int cnt = 0;
    for (int k = tid; k < n; k += 256) { const float ev = __expf(row[k] - m); e[cnt++] = ev; sum += ev; }
    red[tid] = sum; __syncthreads();
    for (int s = 128; s > 0; s >>= 1) {
        if (tid < s) red[tid] += red[tid + s];
        __syncthreads();
    }
    const float inv = 1.0f / red[0];

    __nv_bfloat16* ph = g_P_hi + ((size_t)h * TT + q) * TT;
    __nv_bfloat16* pl = g_P_lo + ((size_t)h * TT + q) * TT;
    cnt = 0;
    for (int k = tid; k < npad; k += 256) {
        const float p = (k < n) ? e[cnt++] * inv : 0.f;
        const __nv_bfloat16 hb = __float2bfloat16(p);
        ph[k] = hb;
        pl[k] = __float2bfloat16(p - __bfloat162float(hb));
    }
}

// ============================================================
extern "C" void kernel_launch(void* const* d_in, const int* in_sizes, int n_in,
                              void* d_out, int out_size)
{
    const int*   positions = (const int*)d_in[0];
    const float* hidden    = (const float*)d_in[1];
    const float* Wqkv      = (const float*)d_in[2];
    const float* Wo        = (const float*)d_in[3];
    float*       out       = (float*)d_out;

    float *qkv, *S;
    __nv_bfloat16 *hh, *hl, *wqh, *wql, *woh, *wol, *Qh, *Ql, *Kh, *Kl, *Vth, *Vtl,
                  *Ph, *Pl, *Ath, *Atl;
    cudaGetSymbolAddress((void**)&qkv, g_qkv);
    cudaGetSymbolAddress((void**)&S,   g_S);
    cudaGetSymbolAddress((void**)&hh,  g_hid_hi);  cudaGetSymbolAddress((void**)&hl,  g_hid_lo);
    cudaGetSymbolAddress((void**)&wqh, g_wqkv_hi); cudaGetSymbolAddress((void**)&wql, g_wqkv_lo);
    cudaGetSymbolAddress((void**)&woh, g_wo_hi);   cudaGetSymbolAddress((void**)&wol, g_wo_lo);
    cudaGetSymbolAddress((void**)&Qh,  g_Q_hi);    cudaGetSymbolAddress((void**)&Ql,  g_Q_lo);
    cudaGetSymbolAddress((void**)&Kh,  g_K_hi);    cudaGetSymbolAddress((void**)&Kl,  g_K_lo);
    cudaGetSymbolAddress((void**)&Vth, g_Vt_hi);   cudaGetSymbolAddress((void**)&Vtl, g_Vt_lo);
    cudaGetSymbolAddress((void**)&Ph,  g_P_hi);    cudaGetSymbolAddress((void**)&Pl,  g_P_lo);
    cudaGetSymbolAddress((void**)&Ath, g_attn_hi); cudaGetSymbolAddress((void**)&Atl, g_attn_lo);

    cudaFuncSetAttribute(gemm_mma3<false, false, 0>, cudaFuncAttributeMaxDynamicSharedMemorySize, GEMM_SMEM);
    cudaFuncSetAttribute(gemm_mma3<true,  false, 0>, cudaFuncAttributeMaxDynamicSharedMemorySize, GEMM_SMEM);
    cudaFuncSetAttribute(gemm_mma3<false, true,  1>, cudaFuncAttributeMaxDynamicSharedMemorySize, GEMM_SMEM);

    // 0) fp32 -> bf16 hi/lo planes
    {
        int n1 = TT * HID;   conv_planes<<<(n1 + 255) / 256, 256>>>(hidden, hh, hl, n1);
        int n2 = QKVN * HID; conv_planes<<<(n2 + 255) / 256, 256>>>(Wqkv, wqh, wql, n2);
        int n3 = HID * QS;   conv_planes<<<(n3 + 255) / 256, 256>>>(Wo, woh, wol, n3);
    }

    // 1) qkv = hidden @ Wqkv^T  [2048 x 2560] fp32
    gemm_mma3<false, false, 0><<<dim3(QKVN / 128, TT / 128, 1), 256, GEMM_SMEM>>>(
        hh, hl, wqh, wql, qkv, nullptr, nullptr,
        HID, HID, HID, QKVN, 1.0f, 0, 0, 0);

    // 2) RoPE + split into planes (V transposed)
    rope_split_planes<<<dim3(TT, 10), 128>>>(positions);

    // 3) scores[h] = scale * Q_h @ K^T (causal) -> fp32 g_S
    gemm_mma3<true, false, 0><<<dim3(TT / 128, TT / 128, NHEADS), 256, GEMM_SMEM>>>(
        Qh, Ql, Kh, Kl, S, nullptr, nullptr,
        HD, HD, HD, TT, SCALING, (size_t)TT * HD, 0, (size_t)TT * TT);

    // 4) softmax -> P planes
    softmax_planes<<<dim3(TT, NHEADS), 256>>>();

    // 5) attn[h] = P_h @ Vt^T (block-causal K) -> attn planes [t][h*HD+d]
    gemm_mma3<false, true, 1><<<dim3(HD / 128, TT / 128, NHEADS), 256, GEMM_SMEM>>>(
        Ph, Pl, Vth, Vtl, nullptr, Ath, Atl,
        TT, TT, TT, QS, 1.0f, (size_t)TT * TT, 0, (size_t)HD);

    // 6) out = attn @ Wo^T  [2048 x 2048] fp32
    gemm_mma3<false, false, 0><<<dim3(HID / 128, TT / 128, 1), 256, GEMM_SMEM>>>(
        Ath, Atl, woh, wol, out, nullptr, nullptr,
        QS, QS, QS, HID, 1.0f, 0, 0, 0);
}

// round 6
// speedup vs baseline: 4.1837x; 1.1588x over previous
#include <cuda_runtime.h>
#include <cuda_bf16.h>
#include <math.h>
#include <float.h>
#include <stdint.h>

// ---------------- problem constants ----------------
#define TT      2048
#define HID     2048
#define NHEADS  8
#define HD      256
#define QS      2048
#define KVS     256
#define QKVN    2560
#define SCALING 0.0625f

// ---------------- scratch ----------------
__device__ float g_qkv[(size_t)TT * QKVN];
__device__ float g_S[(size_t)NHEADS * TT * TT];

__device__ __nv_bfloat16 g_hid_hi[(size_t)TT * HID],  g_hid_lo[(size_t)TT * HID];
__device__ __nv_bfloat16 g_wqkv_hi[(size_t)QKVN * HID], g_wqkv_lo[(size_t)QKVN * HID];
__device__ __nv_bfloat16 g_wo_hi[(size_t)HID * QS],   g_wo_lo[(size_t)HID * QS];
__device__ __nv_bfloat16 g_Q_hi[(size_t)NHEADS * TT * HD], g_Q_lo[(size_t)NHEADS * TT * HD];
__device__ __nv_bfloat16 g_K_hi[(size_t)TT * HD],     g_K_lo[(size_t)TT * HD];
__device__ __nv_bfloat16 g_Vt_hi[(size_t)HD * TT],    g_Vt_lo[(size_t)HD * TT];
__device__ __nv_bfloat16 g_P_hi[(size_t)NHEADS * TT * TT], g_P_lo[(size_t)NHEADS * TT * TT];
__device__ __nv_bfloat16 g_attn_hi[(size_t)TT * QS],  g_attn_lo[(size_t)TT * QS];

// ---------------- baseline-PTX helpers ----------------
__device__ __forceinline__ uint32_t smem_to_u32(const void* p) {
    uint32_t a;
    asm("{ .reg .u64 t; cvta.to.shared.u64 t, %1; cvt.u32.u64 %0, t; }" : "=r"(a) : "l"(p));
    return a;
}
#define CP_ASYNC16(dst, src) \
    asm volatile("cp.async.cg.shared.global [%0], [%1], 16;" :: "r"(dst), "l"(src) : "memory")
#define CP_COMMIT() asm volatile("cp.async.commit_group;" ::: "memory")
#define CP_WAIT1()  asm volatile("cp.async.wait_group 1;" ::: "memory")

__device__ __forceinline__ void ldsm_x4(uint32_t& r0, uint32_t& r1, uint32_t& r2, uint32_t& r3,
                                        uint32_t addr) {
    asm volatile("ldmatrix.sync.aligned.m8n8.x4.shared.b16 {%0,%1,%2,%3}, [%4];"
                 : "=r"(r0), "=r"(r1), "=r"(r2), "=r"(r3) : "r"(addr));
}
__device__ __forceinline__ void mma_bf16(float* d, const uint32_t* a, const uint32_t* b) {
    asm volatile("mma.sync.aligned.m16n8k16.row.col.f32.bf16.bf16.f32 "
                 "{%0,%1,%2,%3}, {%4,%5,%6,%7}, {%8,%9}, {%0,%1,%2,%3};"
                 : "+f"(d[0]), "+f"(d[1]), "+f"(d[2]), "+f"(d[3])
                 : "r"(a[0]), "r"(a[1]), "r"(a[2]), "r"(a[3]), "r"(b[0]), "r"(b[1]));
}

// ---------------- smem layout (XOR swizzle, no padding) ----------------
// plane = 128 rows x 64B (32 bf16); addr(row,chunk16) = row*64 + (chunk ^ ((row>>1)&3))*16
// -> the 8 rows of every ldmatrix 8x8 tile hit 8 distinct 16B columns: conflict-free.
#define PLANE_B  8192
#define STAGE    (4 * PLANE_B)       // 32 KB
#define NSTG     3
#define GEMM_SMEM (NSTG * STAGE)     // 96 KB -> 2 CTAs/SM (192 KB of 228 KB)

__device__ __forceinline__ uint32_t sw_addr(uint32_t plane_base, int row, int chunk) {
    return plane_base + row * 64 + ((chunk ^ ((row >> 1) & 3)) << 4);
}

// ============================================================
// 3xBF16 warp-MMA GEMM:  C = alpha * A * B^T
// 128x128 block tile, BK=32, 8 warps (4x2, warp tile 32x64), 2 CTAs/SM.
// 3-stage cp.async pipeline, wait_group 1 (one stage always in flight).
// ============================================================
template<bool CAUSAL, bool CAUSAL_K, int EPI>
__global__ void __launch_bounds__(256, 2) gemm_mma3(
    const __nv_bfloat16* __restrict__ Ahi, const __nv_bfloat16* __restrict__ Alo,
    const __nv_bfloat16* __restrict__ Bhi, const __nv_bfloat16* __restrict__ Blo,
    float* __restrict__ C, __nv_bfloat16* __restrict__ Chi, __nv_bfloat16* __restrict__ Clo,
    int K, int lda, int ldb, int ldc, float alpha,
    size_t sAz, size_t sBz, size_t sCz)
{
    const int r0 = blockIdx.y * 128;
    const int c0 = blockIdx.x * 128;
    if (CAUSAL && c0 > r0 + 127) return;

    extern __shared__ char smem[];
    const uint32_t sb = smem_to_u32(smem);

    const int tid  = threadIdx.x;
    const int wid  = tid >> 5;
    const int lane = tid & 31;
    const int wr   = wid >> 1;
    const int wc   = wid & 1;

    const __nv_bfloat16* gp[4];
    gp[0] = Ahi + blockIdx.z * sAz + (size_t)r0 * lda;
    gp[1] = Alo + blockIdx.z * sAz + (size_t)r0 * lda;
    gp[2] = Bhi + blockIdx.z * sBz + (size_t)c0 * ldb;
    gp[3] = Blo + blockIdx.z * sBz + (size_t)c0 * ldb;
    const int ldp[4] = {lda, lda, ldb, ldb};

    const int kEnd = CAUSAL_K ? (r0 + 128) : K;
    const int nc = kEnd >> 5;

    float acc[2][8][4];
    #pragma unroll
    for (int mi = 0; mi < 2; mi++)
        #pragma unroll
        for (int ni = 0; ni < 8; ni++)
            #pragma unroll
            for (int e = 0; e < 4; e++) acc[mi][ni][e] = 0.f;

    auto prefetch = [&](int ci, int st) {
        const int k0 = ci << 5;
        #pragma unroll
        for (int i = 0; i < 8; i++) {
            const int slot = tid + i * 256;          // 0..2047 16B slots
            const int p    = slot >> 9;              // 512 slots/plane
            const int idx  = slot & 511;
            const int row  = idx >> 2;
            const int chunk = idx & 3;
            const uint32_t daddr = sw_addr(sb + st * STAGE + p * PLANE_B, row, chunk);
            const __nv_bfloat16* src = gp[p] + (size_t)row * ldp[p] + k0 + chunk * 8;
            CP_ASYNC16(daddr, src);
        }
        CP_COMMIT();
    };

    prefetch(0, 0);
    if (nc > 1) prefetch(1, 1);

    const int ldj = lane >> 3;
    const int ldr = lane & 7;

    for (int ci = 0; ci < nc; ci++) {
        CP_WAIT1();              // current stage landed (<=1 group still in flight)
        __syncthreads();
        if (ci + 2 < nc) prefetch(ci + 2, (ci + 2) % NSTG);

        const int st = ci % NSTG;
        const uint32_t Ab = sb + st * STAGE;
        const uint32_t Al = Ab + PLANE_B;
        const uint32_t Bb = Ab + 2 * PLANE_B;
        const uint32_t Bl = Ab + 3 * PLANE_B;

        #pragma unroll
        for (int ks = 0; ks < 2; ks++) {
            uint32_t ah[2][4], al[2][4];
            #pragma unroll
            for (int mi = 0; mi < 2; mi++) {
                const int row = wr * 32 + mi * 16 + (ldj & 1) * 8 + ldr;
                const int ch  = ks * 2 + (ldj >> 1);
                ldsm_x4(ah[mi][0], ah[mi][1], ah[mi][2], ah[mi][3], sw_addr(Ab, row, ch));
                ldsm_x4(al[mi][0], al[mi][1], al[mi][2], al[mi][3], sw_addr(Al, row, ch));
            }
            #pragma unroll
            for (int h2 = 0; h2 < 2; h2++) {
                uint32_t bh[4][2], bl[4][2];
                #pragma unroll
                for (int pi = 0; pi < 2; pi++) {
                    const int row = wc * 64 + h2 * 32 + pi * 16 + (ldj >> 1) * 8 + ldr;
                    const int ch  = ks * 2 + (ldj & 1);
                    ldsm_x4(bh[2 * pi][0], bh[2 * pi][1], bh[2 * pi + 1][0], bh[2 * pi + 1][1],
                            sw_addr(Bb, row, ch));
                    ldsm_x4(bl[2 * pi][0], bl[2 * pi][1], bl[2 * pi + 1][0], bl[2 * pi + 1][1],
                            sw_addr(Bl, row, ch));
                }
                #pragma unroll
                for (int mi = 0; mi < 2; mi++)
                    #pragma unroll
                    for (int nl = 0; nl < 4; nl++)
                        mma_bf16(acc[mi][h2 * 4 + nl], ah[mi], bh[nl]);
                #pragma unroll
                for (int mi = 0; mi < 2; mi++)
                    #pragma unroll
                    for (int nl = 0; nl < 4; nl++)
                        mma_bf16(acc[mi][h2 * 4 + nl], ah[mi], bl[nl]);
                #pragma unroll
                for (int mi = 0; mi < 2; mi++)
                    #pragma unroll
                    for (int nl = 0; nl < 4; nl++)
                        mma_bf16(acc[mi][h2 * 4 + nl], al[mi], bh[nl]);
            }
        }
    }

    // ---- epilogue ----
    const int g = lane >> 2;
    const int t = lane & 3;
    #pragma unroll
    for (int mi = 0; mi < 2; mi++) {
        #pragma unroll
        for (int ni = 0; ni < 8; ni++) {
            const int rr = r0 + wr * 32 + mi * 16 + g;
            const int cc = c0 + wc * 64 + ni * 8 + t * 2;
            #pragma unroll
            for (int half = 0; half < 2; half++) {
                const int r = rr + half * 8;
                float v0 = alpha * acc[mi][ni][half * 2 + 0];
                float v1 = alpha * acc[mi][ni][half * 2 + 1];
                if (CAUSAL) {
                    if (cc + 0 > r) v0 = 0.f;
                    if (cc + 1 > r) v1 = 0.f;
                }
                if (EPI == 0) {
                    float2 v; v.x = v0; v.y = v1;
                    *(float2*)(C + blockIdx.z * sCz + (size_t)r * ldc + cc) = v;
                } else {
                    const __nv_bfloat16 h0 = __float2bfloat16(v0);
                    const __nv_bfloat16 h1 = __float2bfloat16(v1);
                    __nv_bfloat162 hv; hv.x = h0; hv.y = h1;
                    __nv_bfloat162 lv;
                    lv.x = __float2bfloat16(v0 - __bfloat162float(h0));
                    lv.y = __float2bfloat16(v1 - __bfloat162float(h1));
                    *(__nv_bfloat162*)(Chi + blockIdx.z * sCz + (size_t)r * ldc + cc) = hv;
                    *(__nv_bfloat162*)(Clo + blockIdx.z * sCz + (size_t)r * ldc + cc) = lv;
                }
            }
        }
    }
}

// ============================================================
// fp32 -> bf16 hi/lo split (vectorized)
// ============================================================
__global__ void conv_planes(const float* __restrict__ src,
                            __nv_bfloat16* __restrict__ hi, __nv_bfloat16* __restrict__ lo, int n4)
{
    const int i = blockIdx.x * blockDim.x + threadIdx.x;
    if (i < n4) {
        const float4 x = ((const float4*)src)[i];
        __nv_bfloat162 h0, h1, l0, l1;
        h0.x = __float2bfloat16(x.x); h0.y = __float2bfloat16(x.y);
        h1.x = __float2bfloat16(x.z); h1.y = __float2bfloat16(x.w);
        l0.x = __float2bfloat16(x.x - __bfloat162float(h0.x));
        l0.y = __float2bfloat16(x.y - __bfloat162float(h0.y));
        l1.x = __float2bfloat16(x.z - __bfloat162float(h1.x));
        l1.y = __float2bfloat16(x.w - __bfloat162float(h1.y));
        ((__nv_bfloat162*)hi)[2 * i]     = h0;
        ((__nv_bfloat162*)hi)[2 * i + 1] = h1;
        ((__nv_bfloat162*)lo)[2 * i]     = l0;
        ((__nv_bfloat162*)lo)[2 * i + 1] = l1;
    }
}

// ============================================================
// RoPE + split into bf16 hi/lo planes; V transposed.
// ============================================================
__global__ void rope_split_planes(const int* __restrict__ positions)
{
    const int t = blockIdx.x, head = blockIdx.y, i = threadIdx.x;
    const float* base = g_qkv + (size_t)t * QKVN;

    if (head == 9) {
        const float* src = base + QS + KVS;
        #pragma unroll
        for (int hh = 0; hh < 2; hh++) {
            const int d = i + hh * 128;
            const float x = src[d];
            const __nv_bfloat16 h = __float2bfloat16(x);
            g_Vt_hi[(size_t)d * TT + t] = h;
            g_Vt_lo[(size_t)d * TT + t] = __float2bfloat16(x - __bfloat162float(h));
        }
        return;
    }

    const float* src = (head < 8) ? (base + head * HD) : (base + QS);
    const float pos = (float)positions[t];
    const float inv_freq = expf(-((float)(2 * i) / (float)HD) * logf(10000.0f));
    const float ang = pos * inv_freq;
    const float c = cosf(ang), s = sinf(ang);
    const float x1 = src[i], x2 = src[i + 128];
    const float o1 = x1 * c - x2 * s;
    const float o2 = x2 * c + x1 * s;

    __nv_bfloat16 *dh, *dl;
    size_t off;
    if (head < 8) { off = ((size_t)head * TT + t) * HD; dh = g_Q_hi; dl = g_Q_lo; }
    else          { off = (size_t)t * HD;               dh = g_K_hi; dl = g_K_lo; }

    __nv_bfloat16 h1 = __float2bfloat16(o1);
    dh[off + i] = h1;
    dl[off + i] = __float2bfloat16(o1 - __bfloat162float(h1));
    __nv_bfloat16 h2 = __float2bfloat16(o2);
    dh[off + i + 128] = h2;
    dl[off + i + 128] = __float2bfloat16(o2 - __bfloat162float(h2));
}

// ============================================================
// Causal softmax: warp-per-row, smem row cache. One gmem read, one write.
// grid (TT/8, NHEADS), 256 threads (8 warps). dyn smem = 8*2048*4 = 64KB.
// ============================================================
__global__ void __launch_bounds__(256, 2) softmax_planes()
{
    extern __shared__ float xs[];                 // [8][2048]
    const int h = blockIdx.y;
    const int warp = threadIdx.x >> 5, lane = threadIdx.x & 31;
    const int q = blockIdx.x * 8 + warp;
    float* xrow = xs + warp * 2048;

    const float* row = g_S + ((size_t)h * TT + q) * TT;
    const int n = q + 1;
    const int npad = (q & ~127) + 128;

    // pass 1: load + max
    float m = -FLT_MAX;
    for (int k = lane * 4; k < n; k += 128) {
        const float4 v = *(const float4*)(row + k);
        xrow[k + 0] = v.x; xrow[k + 1] = v.y; xrow[k + 2] = v.z; xrow[k + 3] = v.w;
        if (k + 0 < n) m = fmaxf(m, v.x);
        if (k + 1 < n) m = fmaxf(m, v.y);
        if (k + 2 < n) m = fmaxf(m, v.z);
        if (k + 3 < n) m = fmaxf(m, v.w);
    }
    #pragma unroll
    for (int o = 16; o > 0; o >>= 1) m = fmaxf(m, __shfl_xor_sync(0xFFFFFFFFu, m, o));

    // pass 2: exp + sum (store e back to smem)
    float sum = 0.f;
    for (int k = lane * 4; k < n; k += 128) {
        #pragma unroll
        for (int j = 0; j < 4; j++) {
            const float e = (k + j < n) ? __expf(xrow[k + j] - m) : 0.f;
            xrow[k + j] = e;
            sum += e;
        }
    }
    #pragma unroll
    for (int o = 16; o > 0; o >>= 1) sum += __shfl_xor_sync(0xFFFFFFFFu, sum, o);
    const float inv = 1.0f / sum;

    // pass 3: normalize + split planes (zero-pad to 128 boundary)
    __nv_bfloat16* ph = g_P_hi + ((size_t)h * TT + q) * TT;
    __nv_bfloat16* pl = g_P_lo + ((size_t)h * TT + q) * TT;
    for (int k = lane * 4; k < npad; k += 128) {
        __nv_bfloat162 hv0, lv0, hv1, lv1;
        #pragma unroll
        for (int j = 0; j < 4; j++) {
            const float p = (k + j < n) ? xrow[k + j] * inv : 0.f;
            const __nv_bfloat16 hb = __float2bfloat16(p);
            const __nv_bfloat16 lb = __float2bfloat16(p - __bfloat162float(hb));
            if (j == 0) { hv0.x = hb; lv0.x = lb; }
            if (j == 1) { hv0.y = hb; lv0.y = lb; }
            if (j == 2) { hv1.x = hb; lv1.x = lb; }
            if (j == 3) { hv1.y = hb; lv1.y = lb; }
        }
        *(__nv_bfloat162*)(ph + k)     = hv0;
        *(__nv_bfloat162*)(ph + k + 2) = hv1;
        *(__nv_bfloat162*)(pl + k)     = lv0;
        *(__nv_bfloat162*)(pl + k + 2) = lv1;
    }
}

// ============================================================
extern "C" void kernel_launch(void* const* d_in, const int* in_sizes, int n_in,
                              void* d_out, int out_size)
{
    const int*   positions = (const int*)d_in[0];
    const float* hidden    = (const float*)d_in[1];
    const float* Wqkv      = (const float*)d_in[2];
    const float* Wo        = (const float*)d_in[3];
    float*       out       = (float*)d_out;

    float *qkv, *S;
    __nv_bfloat16 *hh, *hl, *wqh, *wql, *woh, *wol, *Qh, *Ql, *Kh, *Kl, *Vth, *Vtl,
                  *Ph, *Pl, *Ath, *Atl;
    cudaGetSymbolAddress((void**)&qkv, g_qkv);
    cudaGetSymbolAddress((void**)&S,   g_S);
    cudaGetSymbolAddress((void**)&hh,  g_hid_hi);  cudaGetSymbolAddress((void**)&hl,  g_hid_lo);
    cudaGetSymbolAddress((void**)&wqh, g_wqkv_hi); cudaGetSymbolAddress((void**)&wql, g_wqkv_lo);
    cudaGetSymbolAddress((void**)&woh, g_wo_hi);   cudaGetSymbolAddress((void**)&wol, g_wo_lo);
    cudaGetSymbolAddress((void**)&Qh,  g_Q_hi);    cudaGetSymbolAddress((void**)&Ql,  g_Q_lo);
    cudaGetSymbolAddress((void**)&Kh,  g_K_hi);    cudaGetSymbolAddress((void**)&Kl,  g_K_lo);
    cudaGetSymbolAddress((void**)&Vth, g_Vt_hi);   cudaGetSymbolAddress((void**)&Vtl, g_Vt_lo);
    cudaGetSymbolAddress((void**)&Ph,  g_P_hi);    cudaGetSymbolAddress((void**)&Pl,  g_P_lo);
    cudaGetSymbolAddress((void**)&Ath, g_attn_hi); cudaGetSymbolAddress((void**)&Atl, g_attn_lo);

    cudaFuncSetAttribute(gemm_mma3<false, false, 0>, cudaFuncAttributeMaxDynamicSharedMemorySize, GEMM_SMEM);
    cudaFuncSetAttribute(gemm_mma3<true,  false, 0>, cudaFuncAttributeMaxDynamicSharedMemorySize, GEMM_SMEM);
    cudaFuncSetAttribute(gemm_mma3<false, true,  1>, cudaFuncAttributeMaxDynamicSharedMemorySize, GEMM_SMEM);
    cudaFuncSetAttribute(softmax_planes, cudaFuncAttributeMaxDynamicSharedMemorySize, 65536);

    // 0) fp32 -> bf16 hi/lo planes
    {
        int n1 = TT * HID / 4;   conv_planes<<<(n1 + 255) / 256, 256>>>(hidden, hh, hl, n1);
        int n2 = QKVN * HID / 4; conv_planes<<<(n2 + 255) / 256, 256>>>(Wqkv, wqh, wql, n2);
        int n3 = HID * QS / 4;   conv_planes<<<(n3 + 255) / 256, 256>>>(Wo, woh, wol, n3);
    }

    // 1) qkv = hidden @ Wqkv^T
    gemm_mma3<false, false, 0><<<dim3(QKVN / 128, TT / 128, 1), 256, GEMM_SMEM>>>(
        hh, hl, wqh, wql, qkv, nullptr, nullptr,
        HID, HID, HID, QKVN, 1.0f, 0, 0, 0);

    // 2) RoPE + split
    rope_split_planes<<<dim3(TT, 10), 128>>>(positions);

    // 3) scores = scale * Q @ K^T (causal)
    gemm_mma3<true, false, 0><<<dim3(TT / 128, TT / 128, NHEADS), 256, GEMM_SMEM>>>(
        Qh, Ql, Kh, Kl, S, nullptr, nullptr,
        HD, HD, HD, TT, SCALING, (size_t)TT * HD, 0, (size_t)TT * TT);

    // 4) softmax -> P planes
    softmax_planes<<<dim3(TT / 8, NHEADS), 256, 65536>>>();

    // 5) attn = P @ Vt^T (block-causal K)
    gemm_mma3<false, true, 1><<<dim3(HD / 128, TT / 128, NHEADS), 256, GEMM_SMEM>>>(
        Ph, Pl, Vth, Vtl, nullptr, Ath, Atl,
        TT, TT, TT, QS, 1.0f, (size_t)TT * TT, 0, (size_t)HD);

    // 6) out = attn @ Wo^T
    gemm_mma3<false, false, 0><<<dim3(HID / 128, TT / 128, 1), 256, GEMM_SMEM>>>(
        Ath, Atl, woh, wol, out, nullptr, nullptr,
        QS, QS, QS, HID, 1.0f, 0, 0, 0);
}

// round 7
// speedup vs baseline: 4.5439x; 1.0861x over previous
#include <cuda_runtime.h>
#include <cuda_bf16.h>
#include <math.h>
#include <float.h>
#include <stdint.h>

// ---------------- problem constants ----------------
#define TT      2048
#define HID     2048
#define NHEADS  8
#define HD      256
#define QS      2048
#define KVS     256
#define QKVN    2560
#define SCALING 0.0625f

// ---------------- scratch ----------------
__device__ float g_qkv[(size_t)TT * QKVN];
__device__ float g_S[(size_t)NHEADS * TT * TT];
__device__ float g_pv_part[2][(size_t)TT * QS];      // split-K partials for P*V

__device__ __nv_bfloat16 g_hid_hi[(size_t)TT * HID],  g_hid_lo[(size_t)TT * HID];
__device__ __nv_bfloat16 g_wqkv_hi[(size_t)QKVN * HID], g_wqkv_lo[(size_t)QKVN * HID];
__device__ __nv_bfloat16 g_wo_hi[(size_t)HID * QS],   g_wo_lo[(size_t)HID * QS];
__device__ __nv_bfloat16 g_Q_hi[(size_t)NHEADS * TT * HD], g_Q_lo[(size_t)NHEADS * TT * HD];
__device__ __nv_bfloat16 g_K_hi[(size_t)TT * HD],     g_K_lo[(size_t)TT * HD];
__device__ __nv_bfloat16 g_Vt_hi[(size_t)HD * TT],    g_Vt_lo[(size_t)HD * TT];
__device__ __nv_bfloat16 g_P_hi[(size_t)NHEADS * TT * TT], g_P_lo[(size_t)NHEADS * TT * TT];
__device__ __nv_bfloat16 g_attn_hi[(size_t)TT * QS],  g_attn_lo[(size_t)TT * QS];

// ---------------- baseline-PTX helpers ----------------
__device__ __forceinline__ uint32_t smem_to_u32(const void* p) {
    uint32_t a;
    asm("{ .reg .u64 t; cvta.to.shared.u64 t, %1; cvt.u32.u64 %0, t; }" : "=r"(a) : "l"(p));
    return a;
}
#define CP_ASYNC16(dst, src) \
    asm volatile("cp.async.cg.shared.global [%0], [%1], 16;" :: "r"(dst), "l"(src) : "memory")
#define CP_COMMIT() asm volatile("cp.async.commit_group;" ::: "memory")
#define CP_WAIT1()  asm volatile("cp.async.wait_group 1;" ::: "memory")

__device__ __forceinline__ void ldsm_x4(uint32_t& r0, uint32_t& r1, uint32_t& r2, uint32_t& r3,
                                        uint32_t addr) {
    asm volatile("ldmatrix.sync.aligned.m8n8.x4.shared.b16 {%0,%1,%2,%3}, [%4];"
                 : "=r"(r0), "=r"(r1), "=r"(r2), "=r"(r3) : "r"(addr));
}
__device__ __forceinline__ void mma_bf16(float* d, const uint32_t* a, const uint32_t* b) {
    asm volatile("mma.sync.aligned.m16n8k16.row.col.f32.bf16.bf16.f32 "
                 "{%0,%1,%2,%3}, {%4,%5,%6,%7}, {%8,%9}, {%0,%1,%2,%3};"
                 : "+f"(d[0]), "+f"(d[1]), "+f"(d[2]), "+f"(d[3])
                 : "r"(a[0]), "r"(a[1]), "r"(a[2]), "r"(a[3]), "r"(b[0]), "r"(b[1]));
}

// XOR-swizzled plane: row*64B + (chunk ^ ((row>>1)&3))*16 -> conflict-free ldmatrix
__device__ __forceinline__ uint32_t sw_addr(uint32_t plane_base, int row, int chunk) {
    return plane_base + row * 64 + ((chunk ^ ((row >> 1) & 3)) << 4);
}
#define NSTG 3

// ============================================================
// 3xBF16 warp-MMA GEMM:  C = alpha * A * B^T
// Block tile (MT*64) x 128, BK=32, 8 warps (4 x 2; warp tile (MT*16) x 64).
// MT=2: 128-row tiles (96KB smem); MT=1: 64-row tiles (72KB smem).
// SPLITK: blockIdx.z = head*2+split, y reversed (big K first), K range split in half.
// ============================================================
template<bool CAUSAL, bool CAUSAL_K, int EPI, int MT, bool SPLITK>
__global__ void __launch_bounds__(256, 2) gemm_mma3(
    const __nv_bfloat16* __restrict__ Ahi, const __nv_bfloat16* __restrict__ Alo,
    const __nv_bfloat16* __restrict__ Bhi, const __nv_bfloat16* __restrict__ Blo,
    float* __restrict__ C, __nv_bfloat16* __restrict__ Chi, __nv_bfloat16* __restrict__ Clo,
    int K, int lda, int ldb, int ldc, float alpha,
    size_t sAz, size_t sBz, size_t sCz)
{
    constexpr int APLANE = MT * 4096;                 // bytes per A plane
    constexpr int STAGEB = 2 * APLANE + 16384;        // stage bytes
    constexpr int ASLOTS = MT * 256;                  // 16B slots per A plane

    int zz = blockIdx.z, split = 0;
    if (SPLITK) { split = zz & 1; zz >>= 1; }
    const int by = SPLITK ? (gridDim.y - 1 - blockIdx.y) : blockIdx.y;
    const int r0 = by * (MT * 64);
    const int c0 = blockIdx.x * 128;
    if (CAUSAL && c0 > r0 + MT * 64 - 1) return;

    extern __shared__ char smem[];
    const uint32_t sb = smem_to_u32(smem);

    const int tid  = threadIdx.x;
    const int lane = tid & 31;
    const int wid  = tid >> 5;
    const int wr   = wid >> 1;
    const int wc   = wid & 1;

    const __nv_bfloat16* gp[4];
    gp[0] = Ahi + zz * sAz + (size_t)r0 * lda;
    gp[1] = Alo + zz * sAz + (size_t)r0 * lda;
    gp[2] = Bhi + zz * sBz + (size_t)c0 * ldb;
    gp[3] = Blo + zz * sBz + (size_t)c0 * ldb;
    const int ldp[4] = {lda, lda, ldb, ldb};

    int kBeg = 0, kEnd = K;
    if (CAUSAL_K) {
        const int full = r0 + 128;
        kEnd = full;
        if (SPLITK) {
            const int half = full >> 1;               // multiple of 64 -> of 32
            kBeg = split ? half : 0;
            kEnd = split ? full : half;
        }
    }
    const int ncB = kBeg >> 5;
    const int n   = (kEnd - kBeg) >> 5;

    float acc[MT][8][4];
    #pragma unroll
    for (int mi = 0; mi < MT; mi++)
        #pragma unroll
        for (int ni = 0; ni < 8; ni++)
            #pragma unroll
            for (int e = 0; e < 4; e++) acc[mi][ni][e] = 0.f;

    auto prefetch = [&](int j, int st) {
        const int k0 = (ncB + j) << 5;
        const int total = 2 * ASLOTS + 1024;
        #pragma unroll
        for (int s = tid; s < total; s += 256) {
            int p, idx;
            if (s < 2 * ASLOTS) { p = s / ASLOTS; idx = s - p * ASLOTS; }
            else { const int s2 = s - 2 * ASLOTS; p = 2 + (s2 >> 9); idx = s2 & 511; }
            const int row = idx >> 2, chunk = idx & 3;
            const uint32_t pbase = sb + st * STAGEB +
                (p < 2 ? p * APLANE : 2 * APLANE + (p - 2) * 8192);
            const __nv_bfloat16* src = gp[p] + (size_t)row * ldp[p] + k0 + chunk * 8;
            CP_ASYNC16(sw_addr(pbase, row, chunk), src);
        }
        CP_COMMIT();
    };

    prefetch(0, 0);
    if (n > 1) prefetch(1, 1);

    const int ldj = lane >> 3;
    const int ldr = lane & 7;

    for (int j = 0; j < n; j++) {
        CP_WAIT1();
        __syncthreads();
        if (j + 2 < n) prefetch(j + 2, (j + 2) % NSTG);

        const int st = j % NSTG;
        const uint32_t Ab = sb + st * STAGEB;
        const uint32_t Al = Ab + APLANE;
        const uint32_t Bb = Ab + 2 * APLANE;
        const uint32_t Bl = Bb + 8192;

        #pragma unroll
        for (int ks = 0; ks < 2; ks++) {
            uint32_t ah[MT][4], al[MT][4];
            #pragma unroll
            for (int mi = 0; mi < MT; mi++) {
                const int row = wr * (MT * 16) + mi * 16 + (ldj & 1) * 8 + ldr;
                const int ch  = ks * 2 + (ldj >> 1);
                ldsm_x4(ah[mi][0], ah[mi][1], ah[mi][2], ah[mi][3], sw_addr(Ab, row, ch));
                ldsm_x4(al[mi][0], al[mi][1], al[mi][2], al[mi][3], sw_addr(Al, row, ch));
            }
            #pragma unroll
            for (int h2 = 0; h2 < 2; h2++) {
                uint32_t bh[4][2], bl[4][2];
                #pragma unroll
                for (int pi = 0; pi < 2; pi++) {
                    const int row = wc * 64 + h2 * 32 + pi * 16 + (ldj >> 1) * 8 + ldr;
                    const int ch  = ks * 2 + (ldj & 1);
                    ldsm_x4(bh[2 * pi][0], bh[2 * pi][1], bh[2 * pi + 1][0], bh[2 * pi + 1][1],
                            sw_addr(Bb, row, ch));
                    ldsm_x4(bl[2 * pi][0], bl[2 * pi][1], bl[2 * pi + 1][0], bl[2 * pi + 1][1],
                            sw_addr(Bl, row, ch));
                }
                #pragma unroll
                for (int mi = 0; mi < MT; mi++)
                    #pragma unroll
                    for (int nl = 0; nl < 4; nl++)
                        mma_bf16(acc[mi][h2 * 4 + nl], ah[mi], bh[nl]);
                #pragma unroll
                for (int mi = 0; mi < MT; mi++)
                    #pragma unroll
                    for (int nl = 0; nl < 4; nl++)
                        mma_bf16(acc[mi][h2 * 4 + nl], ah[mi], bl[nl]);
                #pragma unroll
                for (int mi = 0; mi < MT; mi++)
                    #pragma unroll
                    for (int nl = 0; nl < 4; nl++)
                        mma_bf16(acc[mi][h2 * 4 + nl], al[mi], bh[nl]);
            }
        }
    }

    // ---- epilogue ----
    float* Cb = C;
    if (SPLITK) Cb += (size_t)split * TT * QS;
    const int g = lane >> 2;
    const int t = lane & 3;
    #pragma unroll
    for (int mi = 0; mi < MT; mi++) {
        #pragma unroll
        for (int ni = 0; ni < 8; ni++) {
            const int rr = r0 + wr * (MT * 16) + mi * 16 + g;
            const int cc = c0 + wc * 64 + ni * 8 + t * 2;
            #pragma unroll
            for (int half = 0; half < 2; half++) {
                const int r = rr + half * 8;
                float v0 = alpha * acc[mi][ni][half * 2 + 0];
                float v1 = alpha * acc[mi][ni][half * 2 + 1];
                if (CAUSAL) {
                    if (cc + 0 > r) v0 = 0.f;
                    if (cc + 1 > r) v1 = 0.f;
                }
                if (EPI == 0) {
                    float2 v; v.x = v0; v.y = v1;
                    *(float2*)(Cb + zz * sCz + (size_t)r * ldc + cc) = v;
                } else {
                    const __nv_bfloat16 h0 = __float2bfloat16(v0);
                    const __nv_bfloat16 h1 = __float2bfloat16(v1);
                    __nv_bfloat162 hv; hv.x = h0; hv.y = h1;
                    __nv_bfloat162 lv;
                    lv.x = __float2bfloat16(v0 - __bfloat162float(h0));
                    lv.y = __float2bfloat16(v1 - __bfloat162float(h1));
                    *(__nv_bfloat162*)(Chi + zz * sCz + (size_t)r * ldc + cc) = hv;
                    *(__nv_bfloat162*)(Clo + zz * sCz + (size_t)r * ldc + cc) = lv;
                }
            }
        }
    }
}

// ============================================================
// fp32 -> bf16 hi/lo split (vectorized)
// ============================================================
__global__ void conv_planes(const float* __restrict__ src,
                            __nv_bfloat16* __restrict__ hi, __nv_bfloat16* __restrict__ lo, int n4)
{
    const int i = blockIdx.x * blockDim.x + threadIdx.x;
    if (i < n4) {
        const float4 x = ((const float4*)src)[i];
        __nv_bfloat162 h0, h1, l0, l1;
        h0.x = __float2bfloat16(x.x); h0.y = __float2bfloat16(x.y);
        h1.x = __float2bfloat16(x.z); h1.y = __float2bfloat16(x.w);
        l0.x = __float2bfloat16(x.x - __bfloat162float(h0.x));
        l0.y = __float2bfloat16(x.y - __bfloat162float(h0.y));
        l1.x = __float2bfloat16(x.z - __bfloat162float(h1.x));
        l1.y = __float2bfloat16(x.w - __bfloat162float(h1.y));
        ((__nv_bfloat162*)hi)[2 * i]     = h0;
        ((__nv_bfloat162*)hi)[2 * i + 1] = h1;
        ((__nv_bfloat162*)lo)[2 * i]     = l0;
        ((__nv_bfloat162*)lo)[2 * i + 1] = l1;
    }
}

// ============================================================
// sum of two fp32 partials -> bf16 hi/lo planes (for split-K P*V)
// ============================================================
__global__ void addconv_planes(const float* __restrict__ a, const float* __restrict__ b,
                               __nv_bfloat16* __restrict__ hi, __nv_bfloat16* __restrict__ lo, int n4)
{
    const int i = blockIdx.x * blockDim.x + threadIdx.x;
    if (i < n4) {
        const float4 xa = ((const float4*)a)[i];
        const float4 xb = ((const float4*)b)[i];
        float x0 = xa.x + xb.x, x1 = xa.y + xb.y, x2 = xa.z + xb.z, x3 = xa.w + xb.w;
        __nv_bfloat162 h0, h1, l0, l1;
        h0.x = __float2bfloat16(x0); h0.y = __float2bfloat16(x1);
        h1.x = __float2bfloat16(x2); h1.y = __float2bfloat16(x3);
        l0.x = __float2bfloat16(x0 - __bfloat162float(h0.x));
        l0.y = __float2bfloat16(x1 - __bfloat162float(h0.y));
        l1.x = __float2bfloat16(x2 - __bfloat162float(h1.x));
        l1.y = __float2bfloat16(x3 - __bfloat162float(h1.y));
        ((__nv_bfloat162*)hi)[2 * i]     = h0;
        ((__nv_bfloat162*)hi)[2 * i + 1] = h1;
        ((__nv_bfloat162*)lo)[2 * i]     = l0;
        ((__nv_bfloat162*)lo)[2 * i + 1] = l1;
    }
}

// ============================================================
// RoPE + split into bf16 hi/lo planes; V transposed.
// ============================================================
__global__ void rope_split_planes(const int* __restrict__ positions)
{
    const int t = blockIdx.x, head = blockIdx.y, i = threadIdx.x;
    const float* base = g_qkv + (size_t)t * QKVN;

    if (head == 9) {
        const float* src = base + QS + KVS;
        #pragma unroll
        for (int hh = 0; hh < 2; hh++) {
            const int d = i + hh * 128;
            const float x = src[d];
            const __nv_bfloat16 h = __float2bfloat16(x);
            g_Vt_hi[(size_t)d * TT + t] = h;
            g_Vt_lo[(size_t)d * TT + t] = __float2bfloat16(x - __bfloat162float(h));
        }
        return;
    }

    const float* src = (head < 8) ? (base + head * HD) : (base + QS);
    const float pos = (float)positions[t];
    const float inv_freq = expf(-((float)(2 * i) / (float)HD) * logf(10000.0f));
    const float ang = pos * inv_freq;
    const float c = cosf(ang), s = sinf(ang);
    const float x1 = src[i], x2 = src[i + 128];
    const float o1 = x1 * c - x2 * s;
    const float o2 = x2 * c + x1 * s;

    __nv_bfloat16 *dh, *dl;
    size_t off;
    if (head < 8) { off = ((size_t)head * TT + t) * HD; dh = g_Q_hi; dl = g_Q_lo; }
    else          { off = (size_t)t * HD;               dh = g_K_hi; dl = g_K_lo; }

    __nv_bfloat16 h1 = __float2bfloat16(o1);
    dh[off + i] = h1;
    dl[off + i] = __float2bfloat16(o1 - __bfloat162float(h1));
    __nv_bfloat16 h2 = __float2bfloat16(o2);
    dh[off + i + 128] = h2;
    dl[off + i + 128] = __float2bfloat16(o2 - __bfloat162float(h2));
}

// ============================================================
// Causal softmax: warp-per-row, smem row cache.
// ============================================================
__global__ void __launch_bounds__(256, 2) softmax_planes()
{
    extern __shared__ float xs[];                 // [8][2048]
    const int h = blockIdx.y;
    const int warp = threadIdx.x >> 5, lane = threadIdx.x & 31;
    const int q = blockIdx.x * 8 + warp;
    float* xrow = xs + warp * 2048;

    const float* row = g_S + ((size_t)h * TT + q) * TT;
    const int n = q + 1;
    const int npad = (q & ~127) + 128;

    float m = -FLT_MAX;
    for (int k = lane * 4; k < n; k += 128) {
        const float4 v = *(const float4*)(row + k);
        xrow[k + 0] = v.x; xrow[k + 1] = v.y; xrow[k + 2] = v.z; xrow[k + 3] = v.w;
        if (k + 0 < n) m = fmaxf(m, v.x);
        if (k + 1 < n) m = fmaxf(m, v.y);
        if (k + 2 < n) m = fmaxf(m, v.z);
        if (k + 3 < n) m = fmaxf(m, v.w);
    }
    #pragma unroll
    for (int o = 16; o > 0; o >>= 1) m = fmaxf(m, __shfl_xor_sync(0xFFFFFFFFu, m, o));

    float sum = 0.f;
    for (int k = lane * 4; k < n; k += 128) {
        #pragma unroll
        for (int j = 0; j < 4; j++) {
            const float e = (k + j < n) ? __expf(xrow[k + j] - m) : 0.f;
            xrow[k + j] = e;
            sum += e;
        }
    }
    #pragma unroll
    for (int o = 16; o > 0; o >>= 1) sum += __shfl_xor_sync(0xFFFFFFFFu, sum, o);
    const float inv = 1.0f / sum;

    __nv_bfloat16* ph = g_P_hi + ((size_t)h * TT + q) * TT;
    __nv_bfloat16* pl = g_P_lo + ((size_t)h * TT + q) * TT;
    for (int k = lane * 4; k < npad; k += 128) {
        __nv_bfloat162 hv0, lv0, hv1, lv1;
        #pragma unroll
        for (int j = 0; j < 4; j++) {
            const float p = (k + j < n) ? xrow[k + j] * inv : 0.f;
            const __nv_bfloat16 hb = __float2bfloat16(p);
            const __nv_bfloat16 lb = __float2bfloat16(p - __bfloat162float(hb));
            if (j == 0) { hv0.x = hb; lv0.x = lb; }
            if (j == 1) { hv0.y = hb; lv0.y = lb; }
            if (j == 2) { hv1.x = hb; lv1.x = lb; }
            if (j == 3) { hv1.y = hb; lv1.y = lb; }
        }
        *(__nv_bfloat162*)(ph + k)     = hv0;
        *(__nv_bfloat162*)(ph + k + 2) = hv1;
        *(__nv_bfloat162*)(pl + k)     = lv0;
        *(__nv_bfloat162*)(pl + k + 2) = lv1;
    }
}

// ============================================================
extern "C" void kernel_launch(void* const* d_in, const int* in_sizes, int n_in,
                              void* d_out, int out_size)
{
    const int*   positions = (const int*)d_in[0];
    const float* hidden    = (const float*)d_in[1];
    const float* Wqkv      = (const float*)d_in[2];
    const float* Wo        = (const float*)d_in[3];
    float*       out       = (float*)d_out;

    float *qkv, *S, *pvp;
    __nv_bfloat16 *hh, *hl, *wqh, *wql, *woh, *wol, *Qh, *Ql, *Kh, *Kl, *Vth, *Vtl,
                  *Ph, *Pl, *Ath, *Atl;
    cudaGetSymbolAddress((void**)&qkv, g_qkv);
    cudaGetSymbolAddress((void**)&S,   g_S);
    cudaGetSymbolAddress((void**)&pvp, g_pv_part);
    cudaGetSymbolAddress((void**)&hh,  g_hid_hi);  cudaGetSymbolAddress((void**)&hl,  g_hid_lo);
    cudaGetSymbolAddress((void**)&wqh, g_wqkv_hi); cudaGetSymbolAddress((void**)&wql, g_wqkv_lo);
    cudaGetSymbolAddress((void**)&woh, g_wo_hi);   cudaGetSymbolAddress((void**)&wol, g_wo_lo);
    cudaGetSymbolAddress((void**)&Qh,  g_Q_hi);    cudaGetSymbolAddress((void**)&Ql,  g_Q_lo);
    cudaGetSymbolAddress((void**)&Kh,  g_K_hi);    cudaGetSymbolAddress((void**)&Kl,  g_K_lo);
    cudaGetSymbolAddress((void**)&Vth, g_Vt_hi);   cudaGetSymbolAddress((void**)&Vtl, g_Vt_lo);
    cudaGetSymbolAddress((void**)&Ph,  g_P_hi);    cudaGetSymbolAddress((void**)&Pl,  g_P_lo);
    cudaGetSymbolAddress((void**)&Ath, g_attn_hi); cudaGetSymbolAddress((void**)&Atl, g_attn_lo);

    const int SMEM_MT1 = NSTG * (2 * 4096 + 16384);   // 73728
    const int SMEM_MT2 = NSTG * (2 * 8192 + 16384);   // 98304

    cudaFuncSetAttribute(gemm_mma3<false, false, 0, 1, false>, cudaFuncAttributeMaxDynamicSharedMemorySize, SMEM_MT1);
    cudaFuncSetAttribute(gemm_mma3<true,  false, 0, 2, false>, cudaFuncAttributeMaxDynamicSharedMemorySize, SMEM_MT2);
    cudaFuncSetAttribute(gemm_mma3<false, true,  0, 2, true>,  cudaFuncAttributeMaxDynamicSharedMemorySize, SMEM_MT2);
    cudaFuncSetAttribute(gemm_mma3<false, false, 0, 2, false>, cudaFuncAttributeMaxDynamicSharedMemorySize, SMEM_MT2);
    cudaFuncSetAttribute(softmax_planes, cudaFuncAttributeMaxDynamicSharedMemorySize, 65536);

    // 0) fp32 -> bf16 hi/lo planes
    {
        int n1 = TT * HID / 4;   conv_planes<<<(n1 + 255) / 256, 256>>>(hidden, hh, hl, n1);
        int n2 = QKVN * HID / 4; conv_planes<<<(n2 + 255) / 256, 256>>>(Wqkv, wqh, wql, n2);
        int n3 = HID * QS / 4;   conv_planes<<<(n3 + 255) / 256, 256>>>(Wo, woh, wol, n3);
    }

    // 1) qkv = hidden @ Wqkv^T -- 64x128 tiles (640 CTAs: better wave fit)
    gemm_mma3<false, false, 0, 1, false><<<dim3(QKVN / 128, TT / 64, 1), 256, SMEM_MT1>>>(
        hh, hl, wqh, wql, qkv, nullptr, nullptr,
        HID, HID, HID, QKVN, 1.0f, 0, 0, 0);

    // 2) RoPE + split
    rope_split_planes<<<dim3(TT, 10), 128>>>(positions);

    // 3) scores = scale * Q @ K^T (causal)
    gemm_mma3<true, false, 0, 2, false><<<dim3(TT / 128, TT / 128, NHEADS), 256, SMEM_MT2>>>(
        Qh, Ql, Kh, Kl, S, nullptr, nullptr,
        HD, HD, HD, TT, SCALING, (size_t)TT * HD, 0, (size_t)TT * TT);

    // 4) softmax -> P planes
    softmax_planes<<<dim3(TT / 8, NHEADS), 256, 65536>>>();

    // 5) attn partials = P @ Vt^T (block-causal K, split-K x2, big rows first)
    gemm_mma3<false, true, 0, 2, true><<<dim3(HD / 128, TT / 128, NHEADS * 2), 256, SMEM_MT2>>>(
        Ph, Pl, Vth, Vtl, pvp, nullptr, nullptr,
        TT, TT, TT, QS, 1.0f, (size_t)TT * TT, 0, (size_t)HD);

    // 5b) attn = part0 + part1 -> bf16 hi/lo planes
    {
        int n4 = TT * QS / 4;
        addconv_planes<<<(n4 + 255) / 256, 256>>>(pvp, pvp + (size_t)TT * QS, Ath, Atl, n4);
    }

    // 6) out = attn @ Wo^T
    gemm_mma3<false, false, 0, 2, false><<<dim3(HID / 128, TT / 128, 1), 256, SMEM_MT2>>>(
        Ath, Atl, woh, wol, out, nullptr, nullptr,
        QS, QS, QS, HID, 1.0f, 0, 0, 0);
}

// round 8
// speedup vs baseline: 4.7472x; 1.0447x over previous
#include <cuda_runtime.h>
#include <cuda_bf16.h>
#include <math.h>
#include <float.h>
#include <stdint.h>

// ---------------- problem constants ----------------
#define TT      2048
#define HID     2048
#define NHEADS  8
#define HD      256
#define QS      2048
#define KVS     256
#define QKVN    2560
#define SCALING 0.0625f

// ---------------- scratch ----------------
// g_S doubles as: (early) qkv split-K partials [2][TT*QKVN] fp32; (later) scores.
__device__ float g_S[(size_t)NHEADS * TT * TT];
__device__ float g_pv_part[2][(size_t)TT * QS];

__device__ __nv_bfloat16 g_hid_hi[(size_t)TT * HID],  g_hid_lo[(size_t)TT * HID];
__device__ __nv_bfloat16 g_wqkv_hi[(size_t)QKVN * HID], g_wqkv_lo[(size_t)QKVN * HID];
__device__ __nv_bfloat16 g_wo_hi[(size_t)HID * QS],   g_wo_lo[(size_t)HID * QS];
__device__ __nv_bfloat16 g_Q_hi[(size_t)NHEADS * TT * HD], g_Q_lo[(size_t)NHEADS * TT * HD];
__device__ __nv_bfloat16 g_K_hi[(size_t)TT * HD],     g_K_lo[(size_t)TT * HD];
__device__ __nv_bfloat16 g_Vt_hi[(size_t)HD * TT],    g_Vt_lo[(size_t)HD * TT];
__device__ __nv_bfloat16 g_P_hi[(size_t)NHEADS * TT * TT], g_P_lo[(size_t)NHEADS * TT * TT];
__device__ __nv_bfloat16 g_attn_hi[(size_t)TT * QS],  g_attn_lo[(size_t)TT * QS];

// ---------------- baseline-PTX helpers ----------------
__device__ __forceinline__ uint32_t smem_to_u32(const void* p) {
    uint32_t a;
    asm("{ .reg .u64 t; cvta.to.shared.u64 t, %1; cvt.u32.u64 %0, t; }" : "=r"(a) : "l"(p));
    return a;
}
#define CP_ASYNC16(dst, src) \
    asm volatile("cp.async.cg.shared.global [%0], [%1], 16;" :: "r"(dst), "l"(src) : "memory")
#define CP_COMMIT() asm volatile("cp.async.commit_group;" ::: "memory")
#define CP_WAIT1()  asm volatile("cp.async.wait_group 1;" ::: "memory")

__device__ __forceinline__ void ldsm_x4(uint32_t& r0, uint32_t& r1, uint32_t& r2, uint32_t& r3,
                                        uint32_t addr) {
    asm volatile("ldmatrix.sync.aligned.m8n8.x4.shared.b16 {%0,%1,%2,%3}, [%4];"
                 : "=r"(r0), "=r"(r1), "=r"(r2), "=r"(r3) : "r"(addr));
}
__device__ __forceinline__ void mma_bf16(float* d, const uint32_t* a, const uint32_t* b) {
    asm volatile("mma.sync.aligned.m16n8k16.row.col.f32.bf16.bf16.f32 "
                 "{%0,%1,%2,%3}, {%4,%5,%6,%7}, {%8,%9}, {%0,%1,%2,%3};"
                 : "+f"(d[0]), "+f"(d[1]), "+f"(d[2]), "+f"(d[3])
                 : "r"(a[0]), "r"(a[1]), "r"(a[2]), "r"(a[3]), "r"(b[0]), "r"(b[1]));
}

__device__ __forceinline__ uint32_t sw_addr(uint32_t plane_base, int row, int chunk) {
    return plane_base + row * 64 + ((chunk ^ ((row >> 1) & 3)) << 4);
}
#define NSTG 3

// ============================================================
// 3xBF16 warp-MMA GEMM:  C = alpha * A * B^T
// Block tile (MT*64) x 128, BK=32, 8 warps; MT=2 -> 96KB smem, 2 CTAs/SM.
// SPLITK: z = zz*2+split; K range (CAUSAL_K ? r0+128 : K) halved (32-aligned);
//         partial written to C + split*sSplit. y reversed so big-K tiles start first.
// ============================================================
template<bool CAUSAL, bool CAUSAL_K, int MT, bool SPLITK>
__global__ void __launch_bounds__(256, 2) gemm_mma3(
    const __nv_bfloat16* __restrict__ Ahi, const __nv_bfloat16* __restrict__ Alo,
    const __nv_bfloat16* __restrict__ Bhi, const __nv_bfloat16* __restrict__ Blo,
    float* __restrict__ C, __nv_bfloat16* __restrict__ Chi, __nv_bfloat16* __restrict__ Clo,
    int K, int lda, int ldb, int ldc, float alpha,
    size_t sAz, size_t sBz, size_t sCz, size_t sSplit)
{
    constexpr int APLANE = MT * 4096;
    constexpr int STAGEB = 2 * APLANE + 16384;
    constexpr int ASLOTS = MT * 256;

    int zz = blockIdx.z, split = 0;
    if (SPLITK) { split = zz & 1; zz >>= 1; }
    const int by = SPLITK ? (gridDim.y - 1 - blockIdx.y) : blockIdx.y;
    const int r0 = by * (MT * 64);
    const int c0 = blockIdx.x * 128;
    if (CAUSAL && c0 > r0 + MT * 64 - 1) return;

    extern __shared__ char smem[];
    const uint32_t sb = smem_to_u32(smem);

    const int tid  = threadIdx.x;
    const int lane = tid & 31;
    const int wid  = tid >> 5;
    const int wr   = wid >> 1;
    const int wc   = wid & 1;

    const __nv_bfloat16* gp[4];
    gp[0] = Ahi + zz * sAz + (size_t)r0 * lda;
    gp[1] = Alo + zz * sAz + (size_t)r0 * lda;
    gp[2] = Bhi + zz * sBz + (size_t)c0 * ldb;
    gp[3] = Blo + zz * sBz + (size_t)c0 * ldb;
    const int ldp[4] = {lda, lda, ldb, ldb};

    int kBeg = 0;
    int kEnd = CAUSAL_K ? (r0 + MT * 64) : K;
    if (SPLITK) {
        const int half = (kEnd >> 1) & ~31;
        kBeg = split ? half : 0;
        if (!split) kEnd = half;
    }
    const int ncB = kBeg >> 5;
    const int n   = (kEnd - kBeg) >> 5;

    float acc[MT][8][4];
    #pragma unroll
    for (int mi = 0; mi < MT; mi++)
        #pragma unroll
        for (int ni = 0; ni < 8; ni++)
            #pragma unroll
            for (int e = 0; e < 4; e++) acc[mi][ni][e] = 0.f;

    auto prefetch = [&](int j, int st) {
        const int k0 = (ncB + j) << 5;
        const int total = 2 * ASLOTS + 1024;
        #pragma unroll
        for (int s = tid; s < total; s += 256) {
            int p, idx;
            if (s < 2 * ASLOTS) { p = s / ASLOTS; idx = s - p * ASLOTS; }
            else { const int s2 = s - 2 * ASLOTS; p = 2 + (s2 >> 9); idx = s2 & 511; }
            const int row = idx >> 2, chunk = idx & 3;
            const uint32_t pbase = sb + st * STAGEB +
                (p < 2 ? p * APLANE : 2 * APLANE + (p - 2) * 8192);
            const __nv_bfloat16* src = gp[p] + (size_t)row * ldp[p] + k0 + chunk * 8;
            CP_ASYNC16(sw_addr(pbase, row, chunk), src);
        }
        CP_COMMIT();
    };

    prefetch(0, 0);
    if (n > 1) prefetch(1, 1);

    const int ldj = lane >> 3;
    const int ldr = lane & 7;

    for (int j = 0; j < n; j++) {
        CP_WAIT1();
        __syncthreads();
        if (j + 2 < n) prefetch(j + 2, (j + 2) % NSTG);

        const int st = j % NSTG;
        const uint32_t Ab = sb + st * STAGEB;
        const uint32_t Al = Ab + APLANE;
        const uint32_t Bb = Ab + 2 * APLANE;
        const uint32_t Bl = Bb + 8192;

        #pragma unroll
        for (int ks = 0; ks < 2; ks++) {
            uint32_t ah[MT][4], al[MT][4];
            #pragma unroll
            for (int mi = 0; mi < MT; mi++) {
                const int row = wr * (MT * 16) + mi * 16 + (ldj & 1) * 8 + ldr;
                const int ch  = ks * 2 + (ldj >> 1);
                ldsm_x4(ah[mi][0], ah[mi][1], ah[mi][2], ah[mi][3], sw_addr(Ab, row, ch));
                ldsm_x4(al[mi][0], al[mi][1], al[mi][2], al[mi][3], sw_addr(Al, row, ch));
            }
            #pragma unroll
            for (int h2 = 0; h2 < 2; h2++) {
                uint32_t bh[4][2], bl[4][2];
                #pragma unroll
                for (int pi = 0; pi < 2; pi++) {
                    const int row = wc * 64 + h2 * 32 + pi * 16 + (ldj >> 1) * 8 + ldr;
                    const int ch  = ks * 2 + (ldj & 1);
                    ldsm_x4(bh[2 * pi][0], bh[2 * pi][1], bh[2 * pi + 1][0], bh[2 * pi + 1][1],
                            sw_addr(Bb, row, ch));
                    ldsm_x4(bl[2 * pi][0], bl[2 * pi][1], bl[2 * pi + 1][0], bl[2 * pi + 1][1],
                            sw_addr(Bl, row, ch));
                }
                #pragma unroll
                for (int mi = 0; mi < MT; mi++)
                    #pragma unroll
                    for (int nl = 0; nl < 4; nl++)
                        mma_bf16(acc[mi][h2 * 4 + nl], ah[mi], bh[nl]);
                #pragma unroll
                for (int mi = 0; mi < MT; mi++)
                    #pragma unroll
                    for (int nl = 0; nl < 4; nl++)
                        mma_bf16(acc[mi][h2 * 4 + nl], ah[mi], bl[nl]);
                #pragma unroll
                for (int mi = 0; mi < MT; mi++)
                    #pragma unroll
                    for (int nl = 0; nl < 4; nl++)
                        mma_bf16(acc[mi][h2 * 4 + nl], al[mi], bh[nl]);
            }
        }
    }

    // ---- epilogue ----
    const bool wantF32 = (C != nullptr);
    float* Cb = C;
    if (SPLITK && wantF32) Cb += (size_t)split * sSplit;
    const int g = lane >> 2;
    const int t = lane & 3;
    #pragma unroll
    for (int mi = 0; mi < MT; mi++) {
        #pragma unroll
        for (int ni = 0; ni < 8; ni++) {
            const int rr = r0 + wr * (MT * 16) + mi * 16 + g;
            const int cc = c0 + wc * 64 + ni * 8 + t * 2;
            #pragma unroll
            for (int half = 0; half < 2; half++) {
                const int r = rr + half * 8;
                float v0 = alpha * acc[mi][ni][half * 2 + 0];
                float v1 = alpha * acc[mi][ni][half * 2 + 1];
                if (CAUSAL) {
                    if (cc + 0 > r) v0 = 0.f;
                    if (cc + 1 > r) v1 = 0.f;
                }
                if (wantF32) {
                    float2 v; v.x = v0; v.y = v1;
                    *(float2*)(Cb + zz * sCz + (size_t)r * ldc + cc) = v;
                } else {
                    const __nv_bfloat16 h0 = __float2bfloat16(v0);
                    const __nv_bfloat16 h1 = __float2bfloat16(v1);
                    __nv_bfloat162 hv; hv.x = h0; hv.y = h1;
                    __nv_bfloat162 lv;
                    lv.x = __float2bfloat16(v0 - __bfloat162float(h0));
                    lv.y = __float2bfloat16(v1 - __bfloat162float(h1));
                    *(__nv_bfloat162*)(Chi + zz * sCz + (size_t)r * ldc + cc) = hv;
                    *(__nv_bfloat162*)(Clo + zz * sCz + (size_t)r * ldc + cc) = lv;
                }
            }
        }
    }
}

// ============================================================
__global__ void conv_planes(const float* __restrict__ src,
                            __nv_bfloat16* __restrict__ hi, __nv_bfloat16* __restrict__ lo, int n4)
{
    const int i = blockIdx.x * blockDim.x + threadIdx.x;
    if (i < n4) {
        const float4 x = ((const float4*)src)[i];
        __nv_bfloat162 h0, h1, l0, l1;
        h0.x = __float2bfloat16(x.x); h0.y = __float2bfloat16(x.y);
        h1.x = __float2bfloat16(x.z); h1.y = __float2bfloat16(x.w);
        l0.x = __float2bfloat16(x.x - __bfloat162float(h0.x));
        l0.y = __float2bfloat16(x.y - __bfloat162float(h0.y));
        l1.x = __float2bfloat16(x.z - __bfloat162float(h1.x));
        l1.y = __float2bfloat16(x.w - __bfloat162float(h1.y));
        ((__nv_bfloat162*)hi)[2 * i]     = h0;
        ((__nv_bfloat162*)hi)[2 * i + 1] = h1;
        ((__nv_bfloat162*)lo)[2 * i]     = l0;
        ((__nv_bfloat162*)lo)[2 * i + 1] = l1;
    }
}

// ============================================================
__global__ void addconv_planes(const float* __restrict__ a, const float* __restrict__ b,
                               __nv_bfloat16* __restrict__ hi, __nv_bfloat16* __restrict__ lo, int n4)
{
    const int i = blockIdx.x * blockDim.x + threadIdx.x;
    if (i < n4) {
        const float4 xa = ((const float4*)a)[i];
        const float4 xb = ((const float4*)b)[i];
        float x0 = xa.x + xb.x, x1 = xa.y + xb.y, x2 = xa.z + xb.z, x3 = xa.w + xb.w;
        __nv_bfloat162 h0, h1, l0, l1;
        h0.x = __float2bfloat16(x0); h0.y = __float2bfloat16(x1);
        h1.x = __float2bfloat16(x2); h1.y = __float2bfloat16(x3);
        l0.x = __float2bfloat16(x0 - __bfloat162float(h0.x));
        l0.y = __float2bfloat16(x1 - __bfloat162float(h0.y));
        l1.x = __float2bfloat16(x2 - __bfloat162float(h1.x));
        l1.y = __float2bfloat16(x3 - __bfloat162float(h1.y));
        ((__nv_bfloat162*)hi)[2 * i]     = h0;
        ((__nv_bfloat162*)hi)[2 * i + 1] = h1;
        ((__nv_bfloat162*)lo)[2 * i]     = l0;
        ((__nv_bfloat162*)lo)[2 * i + 1] = l1;
    }
}

// ============================================================
// RoPE + split: sums the two qkv split-K partials (in g_S) inline.
// ============================================================
__global__ void rope_split_planes(const int* __restrict__ positions)
{
    const int t = blockIdx.x, head = blockIdx.y, i = threadIdx.x;
    const float* p0 = g_S + (size_t)t * QKVN;
    const float* p1 = g_S + (size_t)TT * QKVN + (size_t)t * QKVN;

    if (head == 9) {
        #pragma unroll
        for (int hh = 0; hh < 2; hh++) {
            const int d = i + hh * 128;
            const int col = QS + KVS + d;
            const float x = p0[col] + p1[col];
            const __nv_bfloat16 h = __float2bfloat16(x);
            g_Vt_hi[(size_t)d * TT + t] = h;
            g_Vt_lo[(size_t)d * TT + t] = __float2bfloat16(x - __bfloat162float(h));
        }
        return;
    }

    const int cbase = (head < 8) ? head * HD : QS;
    const float pos = (float)positions[t];
    const float inv_freq = expf(-((float)(2 * i) / (float)HD) * logf(10000.0f));
    const float ang = pos * inv_freq;
    const float c = cosf(ang), s = sinf(ang);
    const float x1 = p0[cbase + i]       + p1[cbase + i];
    const float x2 = p0[cbase + i + 128] + p1[cbase + i + 128];
    const float o1 = x1 * c - x2 * s;
    const float o2 = x2 * c + x1 * s;

    __nv_bfloat16 *dh, *dl;
    size_t off;
    if (head < 8) { off = ((size_t)head * TT + t) * HD; dh = g_Q_hi; dl = g_Q_lo; }
    else          { off = (size_t)t * HD;               dh = g_K_hi; dl = g_K_lo; }

    __nv_bfloat16 h1 = __float2bfloat16(o1);
    dh[off + i] = h1;
    dl[off + i] = __float2bfloat16(o1 - __bfloat162float(h1));
    __nv_bfloat16 h2 = __float2bfloat16(o2);
    dh[off + i + 128] = h2;
    dl[off + i + 128] = __float2bfloat16(o2 - __bfloat162float(h2));
}

// ============================================================
// Causal softmax: warp-per-row, smem row cache.
// ============================================================
__global__ void __launch_bounds__(256, 2) softmax_planes()
{
    extern __shared__ float xs[];
    const int h = blockIdx.y;
    const int warp = threadIdx.x >> 5, lane = threadIdx.x & 31;
    const int q = blockIdx.x * 8 + warp;
    float* xrow = xs + warp * 2048;

    const float* row = g_S + ((size_t)h * TT + q) * TT;
    const int n = q + 1;
    const int npad = (q & ~127) + 128;

    float m = -FLT_MAX;
    for (int k = lane * 4; k < n; k += 128) {
        const float4 v = *(const float4*)(row + k);
        xrow[k + 0] = v.x; xrow[k + 1] = v.y; xrow[k + 2] = v.z; xrow[k + 3] = v.w;
        if (k + 0 < n) m = fmaxf(m, v.x);
        if (k + 1 < n) m = fmaxf(m, v.y);
        if (k + 2 < n) m = fmaxf(m, v.z);
        if (k + 3 < n) m = fmaxf(m, v.w);
    }
    #pragma unroll
    for (int o = 16; o > 0; o >>= 1) m = fmaxf(m, __shfl_xor_sync(0xFFFFFFFFu, m, o));

    float sum = 0.f;
    for (int k = lane * 4; k < n; k += 128) {
        #pragma unroll
        for (int j = 0; j < 4; j++) {
            const float e = (k + j < n) ? __expf(xrow[k + j] - m) : 0.f;
            xrow[k + j] = e;
            sum += e;
        }
    }
    #pragma unroll
    for (int o = 16; o > 0; o >>= 1) sum += __shfl_xor_sync(0xFFFFFFFFu, sum, o);
    const float inv = 1.0f / sum;

    __nv_bfloat16* ph = g_P_hi + ((size_t)h * TT + q) * TT;
    __nv_bfloat16* pl = g_P_lo + ((size_t)h * TT + q) * TT;
    for (int k = lane * 4; k < npad; k += 128) {
        __nv_bfloat162 hv0, lv0, hv1, lv1;
        #pragma unroll
        for (int j = 0; j < 4; j++) {
            const float p = (k + j < n) ? xrow[k + j] * inv : 0.f;
            const __nv_bfloat16 hb = __float2bfloat16(p);
            const __nv_bfloat16 lb = __float2bfloat16(p - __bfloat162float(hb));
            if (j == 0) { hv0.x = hb; lv0.x = lb; }
            if (j == 1) { hv0.y = hb; lv0.y = lb; }
            if (j == 2) { hv1.x = hb; lv1.x = lb; }
            if (j == 3) { hv1.y = hb; lv1.y = lb; }
        }
        *(__nv_bfloat162*)(ph + k)     = hv0;
        *(__nv_bfloat162*)(ph + k + 2) = hv1;
        *(__nv_bfloat162*)(pl + k)     = lv0;
        *(__nv_bfloat162*)(pl + k + 2) = lv1;
    }
}

// ============================================================
extern "C" void kernel_launch(void* const* d_in, const int* in_sizes, int n_in,
                              void* d_out, int out_size)
{
    const int*   positions = (const int*)d_in[0];
    const float* hidden    = (const float*)d_in[1];
    const float* Wqkv      = (const float*)d_in[2];
    const float* Wo        = (const float*)d_in[3];
    float*       out       = (float*)d_out;

    float *S, *pvp;
    __nv_bfloat16 *hh, *hl, *wqh, *wql, *woh, *wol, *Qh, *Ql, *Kh, *Kl, *Vth, *Vtl,
                  *Ph, *Pl, *Ath, *Atl;
    cudaGetSymbolAddress((void**)&S,   g_S);
    cudaGetSymbolAddress((void**)&pvp, g_pv_part);
    cudaGetSymbolAddress((void**)&hh,  g_hid_hi);  cudaGetSymbolAddress((void**)&hl,  g_hid_lo);
    cudaGetSymbolAddress((void**)&wqh, g_wqkv_hi); cudaGetSymbolAddress((void**)&wql, g_wqkv_lo);
    cudaGetSymbolAddress((void**)&woh, g_wo_hi);   cudaGetSymbolAddress((void**)&wol, g_wo_lo);
    cudaGetSymbolAddress((void**)&Qh,  g_Q_hi);    cudaGetSymbolAddress((void**)&Ql,  g_Q_lo);
    cudaGetSymbolAddress((void**)&Kh,  g_K_hi);    cudaGetSymbolAddress((void**)&Kl,  g_K_lo);
    cudaGetSymbolAddress((void**)&Vth, g_Vt_hi);   cudaGetSymbolAddress((void**)&Vtl, g_Vt_lo);
    cudaGetSymbolAddress((void**)&Ph,  g_P_hi);    cudaGetSymbolAddress((void**)&Pl,  g_P_lo);
    cudaGetSymbolAddress((void**)&Ath, g_attn_hi); cudaGetSymbolAddress((void**)&Atl, g_attn_lo);

    const int SMEM_MT2 = NSTG * (2 * 8192 + 16384);   // 98304

    cudaFuncSetAttribute(gemm_mma3<false, false, 2, true>,  cudaFuncAttributeMaxDynamicSharedMemorySize, SMEM_MT2);
    cudaFuncSetAttribute(gemm_mma3<true,  false, 2, false>, cudaFuncAttributeMaxDynamicSharedMemorySize, SMEM_MT2);
    cudaFuncSetAttribute(gemm_mma3<false, true,  2, true>,  cudaFuncAttributeMaxDynamicSharedMemorySize, SMEM_MT2);
    cudaFuncSetAttribute(gemm_mma3<false, false, 2, false>, cudaFuncAttributeMaxDynamicSharedMemorySize, SMEM_MT2);
    cudaFuncSetAttribute(softmax_planes, cudaFuncAttributeMaxDynamicSharedMemorySize, 65536);

    // 0) fp32 -> bf16 hi/lo planes
    {
        int n1 = TT * HID / 4;   conv_planes<<<(n1 + 255) / 256, 256>>>(hidden, hh, hl, n1);
        int n2 = QKVN * HID / 4; conv_planes<<<(n2 + 255) / 256, 256>>>(Wqkv, wqh, wql, n2);
        int n3 = HID * QS / 4;   conv_planes<<<(n3 + 255) / 256, 256>>>(Wo, woh, wol, n3);
    }

    // 1) qkv partials = hidden @ Wqkv^T (split-K x2, MT=2) -> g_S[0], g_S[TT*QKVN]
    gemm_mma3<false, false, 2, true><<<dim3(QKVN / 128, TT / 128, 2), 256, SMEM_MT2>>>(
        hh, hl, wqh, wql, S, nullptr, nullptr,
        HID, HID, HID, QKVN, 1.0f, 0, 0, 0, (size_t)TT * QKVN);

    // 2) RoPE + partial-sum + split planes (V transposed)
    rope_split_planes<<<dim3(TT, 10), 128>>>(positions);

    // 3) scores = scale * Q @ K^T (causal) -> g_S (overwrites qkv partials)
    gemm_mma3<true, false, 2, false><<<dim3(TT / 128, TT / 128, NHEADS), 256, SMEM_MT2>>>(
        Qh, Ql, Kh, Kl, S, nullptr, nullptr,
        HD, HD, HD, TT, SCALING, (size_t)TT * HD, 0, (size_t)TT * TT, 0);

    // 4) softmax -> P planes
    softmax_planes<<<dim3(TT / 8, NHEADS), 256, 65536>>>();

    // 5) attn partials = P @ Vt^T (block-causal K, split-K x2)
    gemm_mma3<false, true, 2, true><<<dim3(HD / 128, TT / 128, NHEADS * 2), 256, SMEM_MT2>>>(
        Ph, Pl, Vth, Vtl, pvp, nullptr, nullptr,
        TT, TT, TT, QS, 1.0f, (size_t)TT * TT, 0, (size_t)HD, (size_t)TT * QS);

    // 5b) attn = part0 + part1 -> bf16 hi/lo planes
    {
        int n4 = TT * QS / 4;
        addconv_planes<<<(n4 + 255) / 256, 256>>>(pvp, pvp + (size_t)TT * QS, Ath, Atl, n4);
    }

    // 6) out = attn @ Wo^T
    gemm_mma3<false, false, 2, false><<<dim3(HID / 128, TT / 128, 1), 256, SMEM_MT2>>>(
        Ath, Atl, woh, wol, out, nullptr, nullptr,
        QS, QS, QS, HID, 1.0f, 0, 0, 0, 0);
}